// round 12
// baseline (speedup 1.0000x reference)
#include <cuda_runtime.h>
#include <cuda_bf16.h>
#include <cuda_fp16.h>
#include <math.h>
#include <stdint.h>

// ---------------- problem constants ----------------
constexpr int Bb   = 2;
constexpr int Ss   = 1024;
constexpr int Dd   = 2048;
constexpr int Hh   = 32;
constexpr int HKV  = 8;
constexpr int HDh  = 64;
constexpr int Ee   = 8;
constexpr int Ii   = 1024;
constexpr int Ttok = Bb * Ss;
constexpr int QKVW = (Hh + 2 * HKV) * HDh;    // 3072
constexpr int KOFF = Hh * HDh;                // 2048
constexpr int VOFF = (Hh + HKV) * HDh;        // 2560

// ---------------- scratch ----------------
__device__ float g_qkv [(size_t)Ttok * QKVW];
__device__ float g_h1  [(size_t)Ttok * Dd];
__device__ float g_g   [(size_t)Ttok * Dd];
__device__ float g_shd [(size_t)Ttok * Dd];
__device__ float g_gu  [(size_t)Ee * Ttok * 2048];
__device__ float g_eo  [(size_t)Ee * Ttok * Dd];
__device__ uint32_t g_hH   [(size_t)Ttok * 1024];
__device__ uint32_t g_hL   [(size_t)Ttok * 1024];
__device__ uint32_t g_attnH[(size_t)Ttok * 1024];
__device__ uint32_t g_attnL[(size_t)Ttok * 1024];
__device__ uint32_t g_g16  [(size_t)Ttok * 1024];
__device__ uint32_t g_hid16[(size_t)Ee * Ttok * 512];
__device__ uint32_t g_wqkvH[(size_t)1024 * 3072];
__device__ uint32_t g_wqkvL[(size_t)1024 * 3072];
__device__ uint32_t g_woH  [(size_t)1024 * 2048];
__device__ uint32_t g_woL  [(size_t)1024 * 2048];
__device__ uint32_t g_sg16 [(size_t)1024 * 1024];
__device__ uint32_t g_su16 [(size_t)1024 * 1024];
__device__ uint32_t g_sd16 [(size_t)512 * 2048];
__device__ uint32_t g_wgu16[(size_t)Ee * 1024 * 2048];
__device__ uint32_t g_wdn16[(size_t)Ee * 512 * 2048];
__device__ int   g_cnt [Ee];
__device__ int   g_idx [Ee * Ttok];
__device__ float g_sc  [Ee * Ttok];
__device__ int   g_slot[Ttok * 2];

// ---------------- helpers ----------------
__device__ __forceinline__ void mma_bf16(float c[4], uint32_t a0, uint32_t a1,
                                         uint32_t a2, uint32_t a3,
                                         uint32_t b0, uint32_t b1) {
    asm volatile(
        "mma.sync.aligned.m16n8k16.row.col.f32.bf16.bf16.f32 "
        "{%0,%1,%2,%3}, {%4,%5,%6,%7}, {%8,%9}, {%0,%1,%2,%3};"
        : "+f"(c[0]), "+f"(c[1]), "+f"(c[2]), "+f"(c[3])
        : "r"(a0), "r"(a1), "r"(a2), "r"(a3), "r"(b0), "r"(b1));
}

__device__ __forceinline__ void mma_f16(float c[4], uint32_t a0, uint32_t a1,
                                        uint32_t a2, uint32_t a3,
                                        uint32_t b0, uint32_t b1) {
    asm volatile(
        "mma.sync.aligned.m16n8k16.row.col.f32.f16.f16.f32 "
        "{%0,%1,%2,%3}, {%4,%5,%6,%7}, {%8,%9}, {%0,%1,%2,%3};"
        : "+f"(c[0]), "+f"(c[1]), "+f"(c[2]), "+f"(c[3])
        : "r"(a0), "r"(a1), "r"(a2), "r"(a3), "r"(b0), "r"(b1));
}

__device__ __forceinline__ void bf_split2(float x, float y, uint32_t& hi, uint32_t& lo) {
    __nv_bfloat16 hx = __float2bfloat16_rn(x);
    __nv_bfloat16 hy = __float2bfloat16_rn(y);
    float rx = x - __bfloat162float(hx);
    float ry = y - __bfloat162float(hy);
    __nv_bfloat16 lx = __float2bfloat16_rn(rx);
    __nv_bfloat16 ly = __float2bfloat16_rn(ry);
    hi = (uint32_t)__bfloat16_as_ushort(hx) | ((uint32_t)__bfloat16_as_ushort(hy) << 16);
    lo = (uint32_t)__bfloat16_as_ushort(lx) | ((uint32_t)__bfloat16_as_ushort(ly) << 16);
}

__device__ __forceinline__ uint32_t h2pack(float x, float y) {
    __half2 h = __floats2half2_rn(x, y);
    return *(uint32_t*)&h;
}

// ---------------- conversion kernels (float4-vectorized) ----------------
// f32 [Ktot, N] -> u32 pairs [Ktot/2, N]; each thread does 4 consecutive n
__global__ void convB16_kernel(const float* __restrict__ src, uint32_t* __restrict__ dst,
                               int Nd, long tot4) {
    long i = (long)blockIdx.x * 256 + threadIdx.x;
    if (i >= tot4) return;
    int N4 = Nd >> 2;
    long kp = i / N4;
    int n4 = (int)(i - kp * N4);
    const float* s = src + (size_t)(2 * kp) * Nd + 4 * n4;
    float4 r0 = *(const float4*)s;
    float4 r1 = *(const float4*)(s + Nd);
    uint4 d;
    d.x = h2pack(r0.x, r1.x); d.y = h2pack(r0.y, r1.y);
    d.z = h2pack(r0.z, r1.z); d.w = h2pack(r0.w, r1.w);
    *(uint4*)(dst + (size_t)kp * Nd + 4 * n4) = d;
}

__global__ void convBbf2_kernel(const float* __restrict__ src, uint32_t* __restrict__ hi,
                                uint32_t* __restrict__ lo, int Nd, long tot4) {
    long i = (long)blockIdx.x * 256 + threadIdx.x;
    if (i >= tot4) return;
    int N4 = Nd >> 2;
    long kp = i / N4;
    int n4 = (int)(i - kp * N4);
    const float* s = src + (size_t)(2 * kp) * Nd + 4 * n4;
    float4 r0 = *(const float4*)s;
    float4 r1 = *(const float4*)(s + Nd);
    uint4 dh, dl;
    bf_split2(r0.x, r1.x, dh.x, dl.x);
    bf_split2(r0.y, r1.y, dh.y, dl.y);
    bf_split2(r0.z, r1.z, dh.z, dl.z);
    bf_split2(r0.w, r1.w, dh.w, dl.w);
    *(uint4*)(hi + (size_t)kp * Nd + 4 * n4) = dh;
    *(uint4*)(lo + (size_t)kp * Nd + 4 * n4) = dl;
}

// ---------------- small kernels ----------------
__global__ void zero_cnt_kernel(int* cnt) {
    if (threadIdx.x < Ee) cnt[threadIdx.x] = 0;
}

__global__ void rmsnorm_bf2_kernel(const float* __restrict__ x, const float* __restrict__ w,
                                   uint32_t* __restrict__ hiA, uint32_t* __restrict__ loA) {
    int row = blockIdx.x;
    const float* xr = x + (size_t)row * Dd;
    float ss = 0.f;
    for (int i = threadIdx.x; i < Dd; i += 256) { float v = xr[i]; ss += v * v; }
    __shared__ float red[256];
    red[threadIdx.x] = ss; __syncthreads();
    for (int s = 128; s > 0; s >>= 1) {
        if (threadIdx.x < s) red[threadIdx.x] += red[threadIdx.x + s];
        __syncthreads();
    }
    float inv = rsqrtf(red[0] / (float)Dd + 1e-5f);
    for (int i = threadIdx.x; i < 1024; i += 256) {
        float v0 = xr[2 * i]     * inv * w[2 * i];
        float v1 = xr[2 * i + 1] * inv * w[2 * i + 1];
        uint32_t h, l;
        bf_split2(v0, v1, h, l);
        hiA[(size_t)row * 1024 + i] = h;
        loA[(size_t)row * 1024 + i] = l;
    }
}

__global__ void rmsnorm_f16_kernel(const float* __restrict__ x, const float* __restrict__ w,
                                   float* __restrict__ outF, uint32_t* __restrict__ out16) {
    int row = blockIdx.x;
    const float* xr = x + (size_t)row * Dd;
    float ss = 0.f;
    for (int i = threadIdx.x; i < Dd; i += 256) { float v = xr[i]; ss += v * v; }
    __shared__ float red[256];
    red[threadIdx.x] = ss; __syncthreads();
    for (int s = 128; s > 0; s >>= 1) {
        if (threadIdx.x < s) red[threadIdx.x] += red[threadIdx.x + s];
        __syncthreads();
    }
    float inv = rsqrtf(red[0] / (float)Dd + 1e-5f);
    float* orow = outF + (size_t)row * Dd;
    for (int i = threadIdx.x; i < 1024; i += 256) {
        float v0 = xr[2 * i]     * inv * w[2 * i];
        float v1 = xr[2 * i + 1] * inv * w[2 * i + 1];
        orow[2 * i]     = v0;
        orow[2 * i + 1] = v1;
        out16[(size_t)row * 1024 + i] = h2pack(v0, v1);
    }
}

__global__ void rope_kernel(float* __restrict__ qkv, const float* __restrict__ cache) {
    int idx = blockIdx.x * blockDim.x + threadIdx.x;
    const int TOT = Ttok * 40 * 32;
    if (idx >= TOT) return;
    int p  = idx & 31;
    int hh = (idx >> 5) % 40;
    int t  = idx / (32 * 40);
    int s  = t % Ss;
    float c  = cache[((size_t)s * 32 + p) * 2 + 0];
    float sn = cache[((size_t)s * 32 + p) * 2 + 1];
    float* base = qkv + (size_t)t * QKVW + hh * 64 + 2 * p;
    float x0 = base[0], x1 = base[1];
    base[0] = x0 * c - x1 * sn;
    base[1] = x1 * c + x0 * sn;
}

// ---------------- tensor-core flash attention (bf16x3, pass-reordered) ----------------
constexpr int AST = 36;

__global__ __launch_bounds__(128)
void attn_mma_kernel(const float* __restrict__ qkv,
                     uint32_t* __restrict__ outH, uint32_t* __restrict__ outL) {
    int qt = blockIdx.x, h = blockIdx.y, b = blockIdx.z;
    int tid = threadIdx.x, lane = tid & 31, w = tid >> 5;
    int lr = lane >> 2, lc = lane & 3;
    int kvh = h >> 2;

    __shared__ uint32_t KsH[64 * AST], KsL[64 * AST];
    __shared__ uint32_t VtH[64 * AST], VtL[64 * AST];

    uint32_t qh[4][4], ql[4][4];
    {
        int r0 = qt * 64 + w * 16 + lr;
        const float* q0p = qkv + ((size_t)(b * Ss + r0)) * QKVW + h * 64;
        const float* q1p = q0p + (size_t)8 * QKVW;
#pragma unroll
        for (int ck = 0; ck < 4; ck++) {
            float2 v00 = *(const float2*)(q0p + ck * 16 + 2 * lc);
            float2 v01 = *(const float2*)(q0p + ck * 16 + 8 + 2 * lc);
            float2 v10 = *(const float2*)(q1p + ck * 16 + 2 * lc);
            float2 v11 = *(const float2*)(q1p + ck * 16 + 8 + 2 * lc);
            bf_split2(v00.x * 0.125f, v00.y * 0.125f, qh[ck][0], ql[ck][0]);
            bf_split2(v10.x * 0.125f, v10.y * 0.125f, qh[ck][1], ql[ck][1]);
            bf_split2(v01.x * 0.125f, v01.y * 0.125f, qh[ck][2], ql[ck][2]);
            bf_split2(v11.x * 0.125f, v11.y * 0.125f, qh[ck][3], ql[ck][3]);
        }
    }

    float m0 = -1e30f, m1 = -1e30f, l0 = 0.f, l1 = 0.f;
    float o[8][4];
#pragma unroll
    for (int ni = 0; ni < 8; ni++)
#pragma unroll
        for (int r = 0; r < 4; r++) o[ni][r] = 0.f;

    for (int kt = 0; kt <= qt; kt++) {
        __syncthreads();
        {
            int krow = tid >> 1;
            int d0 = (tid & 1) * 32;
            const float* kp = qkv + ((size_t)(b * Ss + kt * 64 + krow)) * QKVW
                              + KOFF + kvh * 64 + d0;
#pragma unroll
            for (int jj = 0; jj < 16; jj++) {
                float2 v = *(const float2*)(kp + 2 * jj);
                uint32_t hi, lo; bf_split2(v.x, v.y, hi, lo);
                KsH[krow * AST + d0 / 2 + jj] = hi;
                KsL[krow * AST + d0 / 2 + jj] = lo;
            }
            int p = tid & 31, db = (tid >> 5) * 16;
            const float* v0p = qkv + ((size_t)(b * Ss + kt * 64 + 2 * p)) * QKVW
                               + VOFF + kvh * 64 + db;
            const float* v1p = v0p + QKVW;
#pragma unroll
            for (int j = 0; j < 16; j++) {
                uint32_t hi, lo; bf_split2(v0p[j], v1p[j], hi, lo);
                VtH[(db + j) * AST + p] = hi;
                VtL[(db + j) * AST + p] = lo;
            }
        }
        __syncthreads();

        float s[8][4];
#pragma unroll
        for (int ni = 0; ni < 8; ni++)
#pragma unroll
            for (int r = 0; r < 4; r++) s[ni][r] = 0.f;
#pragma unroll
        for (int ck = 0; ck < 4; ck++) {
            uint32_t bh[8][2], bl[8][2];
#pragma unroll
            for (int ni = 0; ni < 8; ni++) {
                int row = (ni * 8 + lr) * AST + ck * 8 + lc;
                bh[ni][0] = KsH[row]; bh[ni][1] = KsH[row + 4];
                bl[ni][0] = KsL[row]; bl[ni][1] = KsL[row + 4];
            }
#pragma unroll
            for (int ni = 0; ni < 8; ni++)
                mma_bf16(s[ni], ql[ck][0], ql[ck][1], ql[ck][2], ql[ck][3],
                         bh[ni][0], bh[ni][1]);
#pragma unroll
            for (int ni = 0; ni < 8; ni++)
                mma_bf16(s[ni], qh[ck][0], qh[ck][1], qh[ck][2], qh[ck][3],
                         bl[ni][0], bl[ni][1]);
#pragma unroll
            for (int ni = 0; ni < 8; ni++)
                mma_bf16(s[ni], qh[ck][0], qh[ck][1], qh[ck][2], qh[ck][3],
                         bh[ni][0], bh[ni][1]);
        }

        if (kt == qt) {
            int lq0 = w * 16 + lr, lq1 = lq0 + 8;
#pragma unroll
            for (int ni = 0; ni < 8; ni++) {
                int col = ni * 8 + 2 * lc;
                if (col     > lq0) s[ni][0] = -1e30f;
                if (col + 1 > lq0) s[ni][1] = -1e30f;
                if (col     > lq1) s[ni][2] = -1e30f;
                if (col + 1 > lq1) s[ni][3] = -1e30f;
            }
        }

        float mt0 = -1e30f, mt1 = -1e30f;
#pragma unroll
        for (int ni = 0; ni < 8; ni++) {
            mt0 = fmaxf(mt0, fmaxf(s[ni][0], s[ni][1]));
            mt1 = fmaxf(mt1, fmaxf(s[ni][2], s[ni][3]));
        }
        mt0 = fmaxf(mt0, __shfl_xor_sync(0xffffffffu, mt0, 1));
        mt0 = fmaxf(mt0, __shfl_xor_sync(0xffffffffu, mt0, 2));
        mt1 = fmaxf(mt1, __shfl_xor_sync(0xffffffffu, mt1, 1));
        mt1 = fmaxf(mt1, __shfl_xor_sync(0xffffffffu, mt1, 2));
        float mn0 = fmaxf(m0, mt0), mn1 = fmaxf(m1, mt1);
        float sc0 = __expf(m0 - mn0), sc1 = __expf(m1 - mn1);
        m0 = mn0; m1 = mn1;

        float rs0 = 0.f, rs1 = 0.f;
#pragma unroll
        for (int ni = 0; ni < 8; ni++) {
            s[ni][0] = __expf(s[ni][0] - m0); rs0 += s[ni][0];
            s[ni][1] = __expf(s[ni][1] - m0); rs0 += s[ni][1];
            s[ni][2] = __expf(s[ni][2] - m1); rs1 += s[ni][2];
            s[ni][3] = __expf(s[ni][3] - m1); rs1 += s[ni][3];
        }
        rs0 += __shfl_xor_sync(0xffffffffu, rs0, 1);
        rs0 += __shfl_xor_sync(0xffffffffu, rs0, 2);
        rs1 += __shfl_xor_sync(0xffffffffu, rs1, 1);
        rs1 += __shfl_xor_sync(0xffffffffu, rs1, 2);
        l0 = l0 * sc0 + rs0;
        l1 = l1 * sc1 + rs1;

#pragma unroll
        for (int ni = 0; ni < 8; ni++) {
            o[ni][0] *= sc0; o[ni][1] *= sc0;
            o[ni][2] *= sc1; o[ni][3] *= sc1;
        }

#pragma unroll
        for (int ck = 0; ck < 4; ck++) {
            uint32_t aH[4], aL[4];
            bf_split2(s[2 * ck][0],     s[2 * ck][1],     aH[0], aL[0]);
            bf_split2(s[2 * ck][2],     s[2 * ck][3],     aH[1], aL[1]);
            bf_split2(s[2 * ck + 1][0], s[2 * ck + 1][1], aH[2], aL[2]);
            bf_split2(s[2 * ck + 1][2], s[2 * ck + 1][3], aH[3], aL[3]);
            uint32_t vh[8][2], vl[8][2];
#pragma unroll
            for (int ni = 0; ni < 8; ni++) {
                int row = (ni * 8 + lr) * AST + ck * 8 + lc;
                vh[ni][0] = VtH[row]; vh[ni][1] = VtH[row + 4];
                vl[ni][0] = VtL[row]; vl[ni][1] = VtL[row + 4];
            }
#pragma unroll
            for (int ni = 0; ni < 8; ni++)
                mma_bf16(o[ni], aL[0], aL[1], aL[2], aL[3], vh[ni][0], vh[ni][1]);
#pragma unroll
            for (int ni = 0; ni < 8; ni++)
                mma_bf16(o[ni], aH[0], aH[1], aH[2], aH[3], vl[ni][0], vl[ni][1]);
#pragma unroll
            for (int ni = 0; ni < 8; ni++)
                mma_bf16(o[ni], aH[0], aH[1], aH[2], aH[3], vh[ni][0], vh[ni][1]);
        }
    }

    float inv0 = 1.f / l0, inv1 = 1.f / l1;
    int t0 = b * Ss + qt * 64 + w * 16 + lr;
    size_t base0 = (size_t)t0 * 1024 + h * 32;
    size_t base1 = base0 + (size_t)8 * 1024;
#pragma unroll
    for (int ni = 0; ni < 8; ni++) {
        int pi = ni * 4 + lc;
        uint32_t h0, l0w, h1, l1w;
        bf_split2(o[ni][0] * inv0, o[ni][1] * inv0, h0, l0w);
        bf_split2(o[ni][2] * inv1, o[ni][3] * inv1, h1, l1w);
        outH[base0 + pi] = h0; outL[base0 + pi] = l0w;
        outH[base1 + pi] = h1; outL[base1 + pi] = l1w;
    }
}

__global__ void router_kernel(const float* __restrict__ g, const float* __restrict__ rw,
                              int* __restrict__ cnt, int* __restrict__ idx,
                              float* __restrict__ sc, int* __restrict__ slot) {
    int t = blockIdx.x;
    int warp = threadIdx.x >> 5, lane = threadIdx.x & 31;
    const float* gr = g + (size_t)t * Dd;
    float acc = 0.f;
    for (int d = lane; d < Dd; d += 32) acc += gr[d] * rw[(size_t)d * Ee + warp];
    for (int o = 16; o; o >>= 1) acc += __shfl_xor_sync(0xffffffffu, acc, o);
    __shared__ float lg[Ee];
    if (lane == 0) lg[warp] = acc;
    __syncthreads();
    if (threadIdx.x == 0) {
        int b1 = 0;
        for (int e = 1; e < Ee; e++) if (lg[e] > lg[b1]) b1 = e;
        int b2 = -1;
        for (int e = 0; e < Ee; e++) {
            if (e == b1) continue;
            if (b2 < 0 || lg[e] > lg[b2]) b2 = e;
        }
        int p1 = atomicAdd(&cnt[b1], 1);
        idx[b1 * Ttok + p1] = t;
        sc [b1 * Ttok + p1] = 1.f / (1.f + expf(-lg[b1]));
        slot[t * 2 + 0] = b1 * Ttok + p1;
        int p2 = atomicAdd(&cnt[b2], 1);
        idx[b2 * Ttok + p2] = t;
        sc [b2 * Ttok + p2] = 1.f / (1.f + expf(-lg[b2]));
        slot[t * 2 + 1] = b2 * Ttok + p2;
    }
}

__global__ void act16_kernel(const float* __restrict__ gu, uint32_t* __restrict__ hid16,
                             const int* __restrict__ cnt) {
    long gidx = (long)blockIdx.x * 256 + threadIdx.x;
    int e = (int)(gidx / ((long)Ttok * 512));
    long rem = gidx % ((long)Ttok * 512);
    int m = (int)(rem >> 9);
    int i2 = (int)(rem & 511);
    int Meff = cnt ? cnt[e] : Ttok;
    if (m >= Meff) return;
    const float* gup = gu + (size_t)e * Ttok * 2048 + (size_t)m * 2048;
    float g0 = gup[2 * i2], g1 = gup[2 * i2 + 1];
    float u0 = gup[1024 + 2 * i2], u1 = gup[1024 + 2 * i2 + 1];
    float v0 = g0 / (1.f + expf(-g0)) * u0;
    float v1 = g1 / (1.f + expf(-g1)) * u1;
    hid16[(size_t)e * Ttok * 512 + (size_t)m * 512 + i2] = h2pack(v0, v1);
}

__global__ void add4_kernel(float* __restrict__ out, const float* __restrict__ h1,
                            const float* __restrict__ shd, const float* __restrict__ eo,
                            const int* __restrict__ slot) {
    int gid = blockIdx.x * 256 + threadIdx.x;
    int t = gid / (Dd / 4);
    int d4 = gid % (Dd / 4);
    size_t off = (size_t)t * Dd + d4 * 4;
    int s0 = slot[t * 2 + 0], s1 = slot[t * 2 + 1];
    float4 a = *(const float4*)(h1 + off);
    float4 b = *(const float4*)(shd + off);
    float4 c0 = *(const float4*)(eo + (size_t)s0 * Dd + d4 * 4);
    float4 c1 = *(const float4*)(eo + (size_t)s1 * Dd + d4 * 4);
    float4 r;
    r.x = a.x + b.x + c0.x + c1.x;
    r.y = a.y + b.y + c0.y + c1.y;
    r.z = a.z + b.z + c0.z + c1.z;
    r.w = a.w + b.w + c0.w + c1.w;
    *(float4*)(out + off) = r;
}

// ---------------- tensor-core GEMM on pre-converted 16-bit pair data ----------------
constexpr int KSTR = 136;

template<int GATHER_A, int CMODE, int PREC>
__global__ __launch_bounds__(128, 2)
void tgemm_kernel(const uint32_t* __restrict__ AH, const uint32_t* __restrict__ AL,
                  const uint32_t* __restrict__ BH, const uint32_t* __restrict__ BL,
                  float* __restrict__ C, const float* __restrict__ Cadd,
                  int M, int N, int K, int ldaP, int ldbN, int ldc,
                  const int* __restrict__ rowIdx, const float* __restrict__ rowScale,
                  const int* __restrict__ cntPtr,
                  long eAstrideP, long eBstrideP, long eCstride,
                  const uint32_t* __restrict__ BselH = nullptr) {
    int e = blockIdx.z;
    int Meff = cntPtr ? cntPtr[e] : M;
    int row0 = blockIdx.y * 128, col0 = blockIdx.x * 128;
    if (row0 >= Meff) return;

    extern __shared__ uint32_t dsm[];
    constexpr int perStage = 2 * 16 * KSTR;

    const int*   rI = rowIdx   ? rowIdx   + (size_t)e * Ttok : nullptr;
    const float* rS = rowScale ? rowScale + (size_t)e * Ttok : nullptr;
    const uint32_t* ApH = AH + (size_t)e * eAstrideP;
    const uint32_t* ApL = (PREC == 2) ? AL + (size_t)e * eAstrideP : nullptr;
    const uint32_t *BpH, *BpL = nullptr;
    float* Cp;
    if (BselH) {
        BpH = e ? BselH : BH;
        Cp = C + (size_t)e * eCstride;
    } else {
        BpH = BH + (size_t)e * eBstrideP;
        if (PREC == 2) BpL = BL + (size_t)e * eBstrideP;
        Cp = C + (size_t)e * eCstride;
    }

    int tid  = threadIdx.x;
    int lane = tid & 31;
    int wid  = tid >> 5;
    int warp_m = (wid & 1) * 64;
    int warp_n = (wid >> 1) * 64;
    int lr = lane >> 2, lc = lane & 3;

    int a_row = tid;
    int gm = row0 + a_row;
    bool avalid = (gm < Meff);
    const uint32_t* arH = ApH;
    const uint32_t* arL = ApL;
    if (avalid) {
        int src = GATHER_A ? rI[gm] : gm;
        arH = ApH + (size_t)src * ldaP;
        if (PREC == 2) arL = ApL + (size_t)src * ldaP;
    }
    int bp   = tid >> 4;
    int bpn0 = (tid & 15) * 8;

    float c[4][8][4];
#pragma unroll
    for (int mi = 0; mi < 4; mi++)
#pragma unroll
        for (int ni = 0; ni < 8; ni++)
#pragma unroll
            for (int r = 0; r < 4; r++) c[mi][ni][r] = 0.f;

    uint4 aW0h, aW1h, aW0l, aW1l, bW0h, bW1h, bW0l, bW1l;

    auto loadStage = [&](int k0) {
        int kp0 = k0 >> 1;
        if (avalid) {
            aW0h = *(const uint4*)(arH + kp0);
            aW1h = *(const uint4*)(arH + kp0 + 4);
            if (PREC == 2) {
                aW0l = *(const uint4*)(arL + kp0);
                aW1l = *(const uint4*)(arL + kp0 + 4);
            }
        } else {
            aW0h = aW1h = make_uint4(0, 0, 0, 0);
            if (PREC == 2) { aW0l = aW1l = make_uint4(0, 0, 0, 0); }
        }
        const uint32_t* br = BpH + (size_t)(kp0 + bp) * ldbN + col0 + bpn0;
        bW0h = *(const uint4*)br;
        bW1h = *(const uint4*)(br + 4);
        if (PREC == 2) {
            const uint32_t* brl = BpL + (size_t)(kp0 + bp) * ldbN + col0 + bpn0;
            bW0l = *(const uint4*)brl;
            bW1l = *(const uint4*)(brl + 4);
        }
    };

    auto storeStage = [&](int s) {
        uint32_t* APH = dsm + s * perStage;
        uint32_t* BPH = APH + 8 * KSTR;
        uint32_t* APL = BPH + 8 * KSTR;
        uint32_t* BPL = APL + 8 * KSTR;
        APH[0 * KSTR + a_row] = aW0h.x;
        APH[1 * KSTR + a_row] = aW0h.y;
        APH[2 * KSTR + a_row] = aW0h.z;
        APH[3 * KSTR + a_row] = aW0h.w;
        APH[4 * KSTR + a_row] = aW1h.x;
        APH[5 * KSTR + a_row] = aW1h.y;
        APH[6 * KSTR + a_row] = aW1h.z;
        APH[7 * KSTR + a_row] = aW1h.w;
        *(uint4*)&BPH[bp * KSTR + bpn0]     = bW0h;
        *(uint4*)&BPH[bp * KSTR + bpn0 + 4] = bW1h;
        if (PREC == 2) {
            APL[0 * KSTR + a_row] = aW0l.x;
            APL[1 * KSTR + a_row] = aW0l.y;
            APL[2 * KSTR + a_row] = aW0l.z;
            APL[3 * KSTR + a_row] = aW0l.w;
            APL[4 * KSTR + a_row] = aW1l.x;
            APL[5 * KSTR + a_row] = aW1l.y;
            APL[6 * KSTR + a_row] = aW1l.z;
            APL[7 * KSTR + a_row] = aW1l.w;
            *(uint4*)&BPL[bp * KSTR + bpn0]     = bW0l;
            *(uint4*)&BPL[bp * KSTR + bpn0 + 4] = bW1l;
        }
    };

    int nk = K >> 4;
    loadStage(0);
    storeStage(0);

    for (int kt = 0; kt < nk; kt++) {
        __syncthreads();
        bool more = (kt + 1) < nk;
        if (more) loadStage((kt + 1) << 4);

        int s = kt & 1;
        uint32_t* APH = dsm + s * perStage;
        uint32_t* BPH = APH + 8 * KSTR;
        uint32_t* APL = BPH + 8 * KSTR;
        uint32_t* BPL = APL + 8 * KSTR;

        uint32_t aH[4][4];
#pragma unroll
        for (int mi = 0; mi < 4; mi++) {
            int r = warp_m + mi * 16 + lr;
            aH[mi][0] = APH[lc * KSTR + r];
            aH[mi][1] = APH[lc * KSTR + r + 8];
            aH[mi][2] = APH[(lc + 4) * KSTR + r];
            aH[mi][3] = APH[(lc + 4) * KSTR + r + 8];
        }
        if (PREC == 1) {
#pragma unroll
            for (int ni = 0; ni < 8; ni++) {
                int cn = warp_n + ni * 8 + lr;
                uint32_t bh0 = BPH[lc * KSTR + cn];
                uint32_t bh1 = BPH[(lc + 4) * KSTR + cn];
#pragma unroll
                for (int mi = 0; mi < 4; mi++)
                    mma_f16(c[mi][ni], aH[mi][0], aH[mi][1], aH[mi][2], aH[mi][3],
                            bh0, bh1);
            }
        } else {
            uint32_t aL[4][4];
#pragma unroll
            for (int mi = 0; mi < 4; mi++) {
                int r = warp_m + mi * 16 + lr;
                aL[mi][0] = APL[lc * KSTR + r];
                aL[mi][1] = APL[lc * KSTR + r + 8];
                aL[mi][2] = APL[(lc + 4) * KSTR + r];
                aL[mi][3] = APL[(lc + 4) * KSTR + r + 8];
            }
            uint32_t bh[8][2], bl[8][2];
#pragma unroll
            for (int ni = 0; ni < 8; ni++) {
                int cn = warp_n + ni * 8 + lr;
                bh[ni][0] = BPH[lc * KSTR + cn];
                bh[ni][1] = BPH[(lc + 4) * KSTR + cn];
                bl[ni][0] = BPL[lc * KSTR + cn];
                bl[ni][1] = BPL[(lc + 4) * KSTR + cn];
            }
            // pass 1: aL * bH   (32 independent MMAs)
#pragma unroll
            for (int ni = 0; ni < 8; ni++)
#pragma unroll
                for (int mi = 0; mi < 4; mi++)
                    mma_bf16(c[mi][ni], aL[mi][0], aL[mi][1], aL[mi][2], aL[mi][3],
                             bh[ni][0], bh[ni][1]);
            // pass 2: aH * bL
#pragma unroll
            for (int ni = 0; ni < 8; ni++)
#pragma unroll
                for (int mi = 0; mi < 4; mi++)
                    mma_bf16(c[mi][ni], aH[mi][0], aH[mi][1], aH[mi][2], aH[mi][3],
                             bl[ni][0], bl[ni][1]);
            // pass 3: aH * bH
#pragma unroll
            for (int ni = 0; ni < 8; ni++)
#pragma unroll
                for (int mi = 0; mi < 4; mi++)
                    mma_bf16(c[mi][ni], aH[mi][0], aH[mi][1], aH[mi][2], aH[mi][3],
                             bh[ni][0], bh[ni][1]);
        }
        if (more) storeStage((kt + 1) & 1);
    }

    // epilogue (rowScale applied here for gathered GEMMs)
#pragma unroll
    for (int mi = 0; mi < 4; mi++) {
        int r0 = row0 + warp_m + mi * 16 + lr;
        int r1 = r0 + 8;
#pragma unroll
        for (int ni = 0; ni < 8; ni++) {
            int cc = col0 + warp_n + ni * 8 + 2 * lc;
            if (r0 < Meff) {
                float s0 = GATHER_A ? rS[r0] : 1.f;
                float v0 = c[mi][ni][0] * s0, v1 = c[mi][ni][1] * s0;
                if (CMODE == 1) {
                    v0 += Cadd[(size_t)r0 * ldc + cc];
                    v1 += Cadd[(size_t)r0 * ldc + cc + 1];
                }
                float* cp = Cp + (size_t)r0 * ldc + cc;
                cp[0] = v0; cp[1] = v1;
            }
            if (r1 < Meff) {
                float s1 = GATHER_A ? rS[r1] : 1.f;
                float v2 = c[mi][ni][2] * s1, v3 = c[mi][ni][3] * s1;
                if (CMODE == 1) {
                    v2 += Cadd[(size_t)r1 * ldc + cc];
                    v3 += Cadd[(size_t)r1 * ldc + cc + 1];
                }
                float* cp = Cp + (size_t)r1 * ldc + cc;
                cp[0] = v2; cp[1] = v3;
            }
        }
    }
}

// ---------------- host orchestration ----------------
extern "C" void kernel_launch(void* const* d_in, const int* in_sizes, int n_in,
                              void* d_out, int out_size) {
    const float* x     = (const float*)d_in[0];
    const float* rope  = (const float*)d_in[2];
    const float* w_qkv = (const float*)d_in[4];
    const float* w_o   = (const float*)d_in[5];
    const float* n1    = (const float*)d_in[6];
    const float* n2    = (const float*)d_in[7];
    const float* rw    = (const float*)d_in[8];
    const float* wgu   = (const float*)d_in[9];
    const float* wdn   = (const float*)d_in[10];
    const float* sg    = (const float*)d_in[11];
    const float* su    = (const float*)d_in[12];
    const float* sd    = (const float*)d_in[13];
    float* out = (float*)d_out;

    float *qkv, *h1, *g, *shd, *gu, *eo, *sc;
    uint32_t *hH, *hL, *attnH, *attnL, *g16, *hid16;
    uint32_t *wqkvH, *wqkvL, *woH, *woL, *sg16, *su16, *sd16, *wgu16, *wdn16;
    int *cnt, *idx, *slot;
    cudaGetSymbolAddress((void**)&qkv,   g_qkv);
    cudaGetSymbolAddress((void**)&h1,    g_h1);
    cudaGetSymbolAddress((void**)&g,     g_g);
    cudaGetSymbolAddress((void**)&shd,   g_shd);
    cudaGetSymbolAddress((void**)&gu,    g_gu);
    cudaGetSymbolAddress((void**)&eo,    g_eo);
    cudaGetSymbolAddress((void**)&hH,    g_hH);
    cudaGetSymbolAddress((void**)&hL,    g_hL);
    cudaGetSymbolAddress((void**)&attnH, g_attnH);
    cudaGetSymbolAddress((void**)&attnL, g_attnL);
    cudaGetSymbolAddress((void**)&g16,   g_g16);
    cudaGetSymbolAddress((void**)&hid16, g_hid16);
    cudaGetSymbolAddress((void**)&wqkvH, g_wqkvH);
    cudaGetSymbolAddress((void**)&wqkvL, g_wqkvL);
    cudaGetSymbolAddress((void**)&woH,   g_woH);
    cudaGetSymbolAddress((void**)&woL,   g_woL);
    cudaGetSymbolAddress((void**)&sg16,  g_sg16);
    cudaGetSymbolAddress((void**)&su16,  g_su16);
    cudaGetSymbolAddress((void**)&sd16,  g_sd16);
    cudaGetSymbolAddress((void**)&wgu16, g_wgu16);
    cudaGetSymbolAddress((void**)&wdn16, g_wdn16);
    cudaGetSymbolAddress((void**)&cnt,   g_cnt);
    cudaGetSymbolAddress((void**)&idx,   g_idx);
    cudaGetSymbolAddress((void**)&sc,    g_sc);
    cudaGetSymbolAddress((void**)&slot,  g_slot);

    const int SMB = 2 * 2 * 16 * KSTR * 4;    // 34816 B

    zero_cnt_kernel<<<1, 32>>>(cnt);

    // ---- one-shot weight conversions (float4-vectorized) ----
    {
        long t1 = (long)1024 * 3072 / 4;
        convBbf2_kernel<<<(t1 + 255) / 256, 256>>>(w_qkv, wqkvH, wqkvL, 3072, t1);
        long t2 = (long)1024 * 2048 / 4;
        convBbf2_kernel<<<(t2 + 255) / 256, 256>>>(w_o, woH, woL, 2048, t2);
        long t3 = (long)1024 * 1024 / 4;
        convB16_kernel<<<(t3 + 255) / 256, 256>>>(sg, sg16, 1024, t3);
        convB16_kernel<<<(t3 + 255) / 256, 256>>>(su, su16, 1024, t3);
        long t4 = (long)512 * 2048 / 4;
        convB16_kernel<<<(t4 + 255) / 256, 256>>>(sd, sd16, 2048, t4);
        long t5 = (long)Ee * 1024 * 2048 / 4;
        convB16_kernel<<<(t5 + 255) / 256, 256>>>(wgu, wgu16, 2048, t5);
        long t6 = (long)Ee * 512 * 2048 / 4;
        convB16_kernel<<<(t6 + 255) / 256, 256>>>(wdn, wdn16, 2048, t6);
    }

    rmsnorm_bf2_kernel<<<Ttok, 256>>>(x, n1, hH, hL);

    // qkv = h @ w_qkv  (bf16x3)
    tgemm_kernel<0, 0, 2><<<dim3(QKVW / 128, Ttok / 128), 128, SMB>>>(
        hH, hL, wqkvH, wqkvL, qkv, nullptr,
        Ttok, QKVW, Dd, 1024, QKVW, QKVW,
        nullptr, nullptr, nullptr, 0, 0, 0);

    rope_kernel<<<(Ttok * 40 * 32 + 255) / 256, 256>>>(qkv, rope);

    attn_mma_kernel<<<dim3(Ss / 64, Hh, Bb), 128>>>(qkv, attnH, attnL);

    // h1 = x + attn @ w_o  (bf16x3)
    tgemm_kernel<0, 1, 2><<<dim3(Dd / 128, Ttok / 128), 128, SMB>>>(
        attnH, attnL, woH, woL, h1, x,
        Ttok, Dd, Dd, 1024, Dd, Dd,
        nullptr, nullptr, nullptr, 0, 0, 0);

    rmsnorm_f16_kernel<<<Ttok, 256>>>(h1, n2, g, g16);

    router_kernel<<<Ttok, 256>>>(g, rw, cnt, idx, sc, slot);

    // shared expert gate & up fused (fp16x1)
    tgemm_kernel<0, 0, 1><<<dim3(Ii / 128, Ttok / 128, 2), 128, SMB>>>(
        g16, nullptr, sg16, nullptr, gu, nullptr,
        Ttok, Ii, Dd, 1024, Ii, 2048,
        nullptr, nullptr, nullptr, 0, 0, 1024, su16);
    act16_kernel<<<(Ttok * 512) / 256, 256>>>(gu, hid16, nullptr);

    // shd = hid_shared @ shared_down (fp16x1)
    tgemm_kernel<0, 0, 1><<<dim3(Dd / 128, Ttok / 128), 128, SMB>>>(
        hid16, nullptr, sd16, nullptr, shd, nullptr,
        Ttok, Dd, Ii, 512, Dd, Dd,
        nullptr, nullptr, nullptr, 0, 0, 0);

    // routed experts gate_up (fp16x1, gathered A; scale in epilogue)
    tgemm_kernel<1, 0, 1><<<dim3(2048 / 128, Ttok / 128, Ee), 128, SMB>>>(
        g16, nullptr, wgu16, nullptr, gu, nullptr,
        Ttok, 2048, Dd, 1024, 2048, 2048,
        idx, sc, cnt, 0, (long)1024 * 2048, (long)Ttok * 2048);

    act16_kernel<<<(Ee * Ttok * 512) / 256, 256>>>(gu, hid16, cnt);

    // routed down projections (fp16x1)
    tgemm_kernel<0, 0, 1><<<dim3(Dd / 128, Ttok / 128, Ee), 128, SMB>>>(
        hid16, nullptr, wdn16, nullptr, eo, nullptr,
        Ttok, Dd, Ii, 512, Dd, Dd,
        nullptr, nullptr, cnt, (long)Ttok * 512, (long)512 * 2048, (long)Ttok * Dd);

    add4_kernel<<<(Ttok * Dd / 4) / 256, 256>>>(out, h1, shd, eo, slot);
}

// round 13
// speedup vs baseline: 1.5135x; 1.5135x over previous
#include <cuda_runtime.h>
#include <cuda_bf16.h>
#include <cuda_fp16.h>
#include <math.h>
#include <stdint.h>

// ---------------- problem constants ----------------
constexpr int Bb   = 2;
constexpr int Ss   = 1024;
constexpr int Dd   = 2048;
constexpr int Hh   = 32;
constexpr int HKV  = 8;
constexpr int HDh  = 64;
constexpr int Ee   = 8;
constexpr int Ii   = 1024;
constexpr int Ttok = Bb * Ss;
constexpr int QKVW = (Hh + 2 * HKV) * HDh;    // 3072
constexpr int KOFF = Hh * HDh;                // 2048
constexpr int VOFF = (Hh + HKV) * HDh;        // 2560

// ---------------- scratch ----------------
__device__ float g_qkv [(size_t)Ttok * QKVW];
__device__ float g_h1  [(size_t)Ttok * Dd];
__device__ float g_g   [(size_t)Ttok * Dd];
__device__ float g_shd [(size_t)Ttok * Dd];
__device__ float g_gu  [(size_t)Ee * Ttok * 2048];
__device__ float g_eo  [(size_t)Ee * Ttok * Dd];
__device__ uint32_t g_hH   [(size_t)Ttok * 1024];
__device__ uint32_t g_hL   [(size_t)Ttok * 1024];
__device__ uint32_t g_attnH[(size_t)Ttok * 1024];
__device__ uint32_t g_attnL[(size_t)Ttok * 1024];
__device__ uint32_t g_g16  [(size_t)Ttok * 1024];
__device__ uint32_t g_hid16[(size_t)Ee * Ttok * 512];
__device__ uint32_t g_wqkvH[(size_t)1024 * 3072];
__device__ uint32_t g_wqkvL[(size_t)1024 * 3072];
__device__ uint32_t g_woH  [(size_t)1024 * 2048];
__device__ uint32_t g_woL  [(size_t)1024 * 2048];
__device__ uint32_t g_sg16 [(size_t)1024 * 1024];
__device__ uint32_t g_su16 [(size_t)1024 * 1024];
__device__ uint32_t g_sd16 [(size_t)512 * 2048];
__device__ uint32_t g_wgu16[(size_t)Ee * 1024 * 2048];
__device__ uint32_t g_wdn16[(size_t)Ee * 512 * 2048];
__device__ int   g_cnt [Ee];
__device__ int   g_idx [Ee * Ttok];
__device__ float g_sc  [Ee * Ttok];
__device__ int   g_slot[Ttok * 2];

// ---------------- helpers ----------------
__device__ __forceinline__ void mma_bf16(float c[4], uint32_t a0, uint32_t a1,
                                         uint32_t a2, uint32_t a3,
                                         uint32_t b0, uint32_t b1) {
    asm volatile(
        "mma.sync.aligned.m16n8k16.row.col.f32.bf16.bf16.f32 "
        "{%0,%1,%2,%3}, {%4,%5,%6,%7}, {%8,%9}, {%0,%1,%2,%3};"
        : "+f"(c[0]), "+f"(c[1]), "+f"(c[2]), "+f"(c[3])
        : "r"(a0), "r"(a1), "r"(a2), "r"(a3), "r"(b0), "r"(b1));
}

__device__ __forceinline__ void mma_f16(float c[4], uint32_t a0, uint32_t a1,
                                        uint32_t a2, uint32_t a3,
                                        uint32_t b0, uint32_t b1) {
    asm volatile(
        "mma.sync.aligned.m16n8k16.row.col.f32.f16.f16.f32 "
        "{%0,%1,%2,%3}, {%4,%5,%6,%7}, {%8,%9}, {%0,%1,%2,%3};"
        : "+f"(c[0]), "+f"(c[1]), "+f"(c[2]), "+f"(c[3])
        : "r"(a0), "r"(a1), "r"(a2), "r"(a3), "r"(b0), "r"(b1));
}

__device__ __forceinline__ void bf_split2(float x, float y, uint32_t& hi, uint32_t& lo) {
    __nv_bfloat16 hx = __float2bfloat16_rn(x);
    __nv_bfloat16 hy = __float2bfloat16_rn(y);
    float rx = x - __bfloat162float(hx);
    float ry = y - __bfloat162float(hy);
    __nv_bfloat16 lx = __float2bfloat16_rn(rx);
    __nv_bfloat16 ly = __float2bfloat16_rn(ry);
    hi = (uint32_t)__bfloat16_as_ushort(hx) | ((uint32_t)__bfloat16_as_ushort(hy) << 16);
    lo = (uint32_t)__bfloat16_as_ushort(lx) | ((uint32_t)__bfloat16_as_ushort(ly) << 16);
}

__device__ __forceinline__ uint32_t h2pack(float x, float y) {
    __half2 h = __floats2half2_rn(x, y);
    return *(uint32_t*)&h;
}

// ---------------- conversion kernels (float4-vectorized, MLP=4) ----------------
// f32 [Ktot, N] -> u32 pairs [Ktot/2, N]; each thread handles 8 consecutive n
__global__ void convB16_kernel(const float* __restrict__ src, uint32_t* __restrict__ dst,
                               int Nd, long tot8) {
    long i = (long)blockIdx.x * 256 + threadIdx.x;
    if (i >= tot8) return;
    int N8 = Nd >> 3;
    long kp = i / N8;
    int n8 = (int)(i - kp * N8);
    const float* s = src + (size_t)(2 * kp) * Nd + 8 * n8;
    float4 r0a = *(const float4*)s;
    float4 r0b = *(const float4*)(s + 4);
    float4 r1a = *(const float4*)(s + Nd);
    float4 r1b = *(const float4*)(s + Nd + 4);
    uint4 da, db;
    da.x = h2pack(r0a.x, r1a.x); da.y = h2pack(r0a.y, r1a.y);
    da.z = h2pack(r0a.z, r1a.z); da.w = h2pack(r0a.w, r1a.w);
    db.x = h2pack(r0b.x, r1b.x); db.y = h2pack(r0b.y, r1b.y);
    db.z = h2pack(r0b.z, r1b.z); db.w = h2pack(r0b.w, r1b.w);
    uint32_t* d = dst + (size_t)kp * Nd + 8 * n8;
    *(uint4*)d = da;
    *(uint4*)(d + 4) = db;
}

__global__ void convBbf2_kernel(const float* __restrict__ src, uint32_t* __restrict__ hi,
                                uint32_t* __restrict__ lo, int Nd, long tot8) {
    long i = (long)blockIdx.x * 256 + threadIdx.x;
    if (i >= tot8) return;
    int N8 = Nd >> 3;
    long kp = i / N8;
    int n8 = (int)(i - kp * N8);
    const float* s = src + (size_t)(2 * kp) * Nd + 8 * n8;
    float4 r0a = *(const float4*)s;
    float4 r0b = *(const float4*)(s + 4);
    float4 r1a = *(const float4*)(s + Nd);
    float4 r1b = *(const float4*)(s + Nd + 4);
    uint4 ha, la, hb, lb;
    bf_split2(r0a.x, r1a.x, ha.x, la.x);
    bf_split2(r0a.y, r1a.y, ha.y, la.y);
    bf_split2(r0a.z, r1a.z, ha.z, la.z);
    bf_split2(r0a.w, r1a.w, ha.w, la.w);
    bf_split2(r0b.x, r1b.x, hb.x, lb.x);
    bf_split2(r0b.y, r1b.y, hb.y, lb.y);
    bf_split2(r0b.z, r1b.z, hb.z, lb.z);
    bf_split2(r0b.w, r1b.w, hb.w, lb.w);
    uint32_t* ph = hi + (size_t)kp * Nd + 8 * n8;
    uint32_t* pl = lo + (size_t)kp * Nd + 8 * n8;
    *(uint4*)ph = ha; *(uint4*)(ph + 4) = hb;
    *(uint4*)pl = la; *(uint4*)(pl + 4) = lb;
}

// ---------------- small kernels ----------------
__global__ void zero_cnt_kernel(int* cnt) {
    if (threadIdx.x < Ee) cnt[threadIdx.x] = 0;
}

__global__ void rmsnorm_bf2_kernel(const float* __restrict__ x, const float* __restrict__ w,
                                   uint32_t* __restrict__ hiA, uint32_t* __restrict__ loA) {
    int row = blockIdx.x;
    const float* xr = x + (size_t)row * Dd;
    float ss = 0.f;
    for (int i = threadIdx.x; i < Dd; i += 256) { float v = xr[i]; ss += v * v; }
    __shared__ float red[256];
    red[threadIdx.x] = ss; __syncthreads();
    for (int s = 128; s > 0; s >>= 1) {
        if (threadIdx.x < s) red[threadIdx.x] += red[threadIdx.x + s];
        __syncthreads();
    }
    float inv = rsqrtf(red[0] / (float)Dd + 1e-5f);
    for (int i = threadIdx.x; i < 1024; i += 256) {
        float v0 = xr[2 * i]     * inv * w[2 * i];
        float v1 = xr[2 * i + 1] * inv * w[2 * i + 1];
        uint32_t h, l;
        bf_split2(v0, v1, h, l);
        hiA[(size_t)row * 1024 + i] = h;
        loA[(size_t)row * 1024 + i] = l;
    }
}

__global__ void rmsnorm_f16_kernel(const float* __restrict__ x, const float* __restrict__ w,
                                   float* __restrict__ outF, uint32_t* __restrict__ out16) {
    int row = blockIdx.x;
    const float* xr = x + (size_t)row * Dd;
    float ss = 0.f;
    for (int i = threadIdx.x; i < Dd; i += 256) { float v = xr[i]; ss += v * v; }
    __shared__ float red[256];
    red[threadIdx.x] = ss; __syncthreads();
    for (int s = 128; s > 0; s >>= 1) {
        if (threadIdx.x < s) red[threadIdx.x] += red[threadIdx.x + s];
        __syncthreads();
    }
    float inv = rsqrtf(red[0] / (float)Dd + 1e-5f);
    float* orow = outF + (size_t)row * Dd;
    for (int i = threadIdx.x; i < 1024; i += 256) {
        float v0 = xr[2 * i]     * inv * w[2 * i];
        float v1 = xr[2 * i + 1] * inv * w[2 * i + 1];
        orow[2 * i]     = v0;
        orow[2 * i + 1] = v1;
        out16[(size_t)row * 1024 + i] = h2pack(v0, v1);
    }
}

__global__ void rope_kernel(float* __restrict__ qkv, const float* __restrict__ cache) {
    int idx = blockIdx.x * blockDim.x + threadIdx.x;
    const int TOT = Ttok * 40 * 32;
    if (idx >= TOT) return;
    int p  = idx & 31;
    int hh = (idx >> 5) % 40;
    int t  = idx / (32 * 40);
    int s  = t % Ss;
    float c  = cache[((size_t)s * 32 + p) * 2 + 0];
    float sn = cache[((size_t)s * 32 + p) * 2 + 1];
    float* base = qkv + (size_t)t * QKVW + hh * 64 + 2 * p;
    float x0 = base[0], x1 = base[1];
    base[0] = x0 * c - x1 * sn;
    base[1] = x1 * c + x0 * sn;
}

// ---------------- tensor-core flash attention (bf16x3, R11 form) ----------------
constexpr int AST = 36;

__global__ __launch_bounds__(128)
void attn_mma_kernel(const float* __restrict__ qkv,
                     uint32_t* __restrict__ outH, uint32_t* __restrict__ outL) {
    int qt = blockIdx.x, h = blockIdx.y, b = blockIdx.z;
    int tid = threadIdx.x, lane = tid & 31, w = tid >> 5;
    int lr = lane >> 2, lc = lane & 3;
    int kvh = h >> 2;

    __shared__ uint32_t KsH[64 * AST], KsL[64 * AST];
    __shared__ uint32_t VtH[64 * AST], VtL[64 * AST];

    uint32_t qh[4][4], ql[4][4];
    {
        int r0 = qt * 64 + w * 16 + lr;
        const float* q0p = qkv + ((size_t)(b * Ss + r0)) * QKVW + h * 64;
        const float* q1p = q0p + (size_t)8 * QKVW;
#pragma unroll
        for (int ck = 0; ck < 4; ck++) {
            float2 v00 = *(const float2*)(q0p + ck * 16 + 2 * lc);
            float2 v01 = *(const float2*)(q0p + ck * 16 + 8 + 2 * lc);
            float2 v10 = *(const float2*)(q1p + ck * 16 + 2 * lc);
            float2 v11 = *(const float2*)(q1p + ck * 16 + 8 + 2 * lc);
            bf_split2(v00.x * 0.125f, v00.y * 0.125f, qh[ck][0], ql[ck][0]);
            bf_split2(v10.x * 0.125f, v10.y * 0.125f, qh[ck][1], ql[ck][1]);
            bf_split2(v01.x * 0.125f, v01.y * 0.125f, qh[ck][2], ql[ck][2]);
            bf_split2(v11.x * 0.125f, v11.y * 0.125f, qh[ck][3], ql[ck][3]);
        }
    }

    float m0 = -1e30f, m1 = -1e30f, l0 = 0.f, l1 = 0.f;
    float o[8][4];
#pragma unroll
    for (int ni = 0; ni < 8; ni++)
#pragma unroll
        for (int r = 0; r < 4; r++) o[ni][r] = 0.f;

    for (int kt = 0; kt <= qt; kt++) {
        __syncthreads();
        {
            int krow = tid >> 1;
            int d0 = (tid & 1) * 32;
            const float* kp = qkv + ((size_t)(b * Ss + kt * 64 + krow)) * QKVW
                              + KOFF + kvh * 64 + d0;
#pragma unroll
            for (int jj = 0; jj < 16; jj++) {
                float2 v = *(const float2*)(kp + 2 * jj);
                uint32_t hi, lo; bf_split2(v.x, v.y, hi, lo);
                KsH[krow * AST + d0 / 2 + jj] = hi;
                KsL[krow * AST + d0 / 2 + jj] = lo;
            }
            int p = tid & 31, db = (tid >> 5) * 16;
            const float* v0p = qkv + ((size_t)(b * Ss + kt * 64 + 2 * p)) * QKVW
                               + VOFF + kvh * 64 + db;
            const float* v1p = v0p + QKVW;
#pragma unroll
            for (int j = 0; j < 16; j++) {
                uint32_t hi, lo; bf_split2(v0p[j], v1p[j], hi, lo);
                VtH[(db + j) * AST + p] = hi;
                VtL[(db + j) * AST + p] = lo;
            }
        }
        __syncthreads();

        float s[8][4];
#pragma unroll
        for (int ni = 0; ni < 8; ni++)
#pragma unroll
            for (int r = 0; r < 4; r++) s[ni][r] = 0.f;
#pragma unroll
        for (int ck = 0; ck < 4; ck++) {
#pragma unroll
            for (int ni = 0; ni < 8; ni++) {
                int row = (ni * 8 + lr) * AST + ck * 8 + lc;
                uint32_t bh0 = KsH[row], bh1 = KsH[row + 4];
                uint32_t bl0 = KsL[row], bl1 = KsL[row + 4];
                mma_bf16(s[ni], ql[ck][0], ql[ck][1], ql[ck][2], ql[ck][3], bh0, bh1);
                mma_bf16(s[ni], qh[ck][0], qh[ck][1], qh[ck][2], qh[ck][3], bl0, bl1);
                mma_bf16(s[ni], qh[ck][0], qh[ck][1], qh[ck][2], qh[ck][3], bh0, bh1);
            }
        }

        if (kt == qt) {
            int lq0 = w * 16 + lr, lq1 = lq0 + 8;
#pragma unroll
            for (int ni = 0; ni < 8; ni++) {
                int col = ni * 8 + 2 * lc;
                if (col     > lq0) s[ni][0] = -1e30f;
                if (col + 1 > lq0) s[ni][1] = -1e30f;
                if (col     > lq1) s[ni][2] = -1e30f;
                if (col + 1 > lq1) s[ni][3] = -1e30f;
            }
        }

        float mt0 = -1e30f, mt1 = -1e30f;
#pragma unroll
        for (int ni = 0; ni < 8; ni++) {
            mt0 = fmaxf(mt0, fmaxf(s[ni][0], s[ni][1]));
            mt1 = fmaxf(mt1, fmaxf(s[ni][2], s[ni][3]));
        }
        mt0 = fmaxf(mt0, __shfl_xor_sync(0xffffffffu, mt0, 1));
        mt0 = fmaxf(mt0, __shfl_xor_sync(0xffffffffu, mt0, 2));
        mt1 = fmaxf(mt1, __shfl_xor_sync(0xffffffffu, mt1, 1));
        mt1 = fmaxf(mt1, __shfl_xor_sync(0xffffffffu, mt1, 2));
        float mn0 = fmaxf(m0, mt0), mn1 = fmaxf(m1, mt1);
        float sc0 = __expf(m0 - mn0), sc1 = __expf(m1 - mn1);
        m0 = mn0; m1 = mn1;

        float rs0 = 0.f, rs1 = 0.f;
#pragma unroll
        for (int ni = 0; ni < 8; ni++) {
            s[ni][0] = __expf(s[ni][0] - m0); rs0 += s[ni][0];
            s[ni][1] = __expf(s[ni][1] - m0); rs0 += s[ni][1];
            s[ni][2] = __expf(s[ni][2] - m1); rs1 += s[ni][2];
            s[ni][3] = __expf(s[ni][3] - m1); rs1 += s[ni][3];
        }
        rs0 += __shfl_xor_sync(0xffffffffu, rs0, 1);
        rs0 += __shfl_xor_sync(0xffffffffu, rs0, 2);
        rs1 += __shfl_xor_sync(0xffffffffu, rs1, 1);
        rs1 += __shfl_xor_sync(0xffffffffu, rs1, 2);
        l0 = l0 * sc0 + rs0;
        l1 = l1 * sc1 + rs1;

#pragma unroll
        for (int ni = 0; ni < 8; ni++) {
            o[ni][0] *= sc0; o[ni][1] *= sc0;
            o[ni][2] *= sc1; o[ni][3] *= sc1;
        }

#pragma unroll
        for (int ck = 0; ck < 4; ck++) {
            uint32_t aH[4], aL[4];
            bf_split2(s[2 * ck][0],     s[2 * ck][1],     aH[0], aL[0]);
            bf_split2(s[2 * ck][2],     s[2 * ck][3],     aH[1], aL[1]);
            bf_split2(s[2 * ck + 1][0], s[2 * ck + 1][1], aH[2], aL[2]);
            bf_split2(s[2 * ck + 1][2], s[2 * ck + 1][3], aH[3], aL[3]);
#pragma unroll
            for (int ni = 0; ni < 8; ni++) {
                int row = (ni * 8 + lr) * AST + ck * 8 + lc;
                uint32_t bh0 = VtH[row], bh1 = VtH[row + 4];
                uint32_t bl0 = VtL[row], bl1 = VtL[row + 4];
                mma_bf16(o[ni], aL[0], aL[1], aL[2], aL[3], bh0, bh1);
                mma_bf16(o[ni], aH[0], aH[1], aH[2], aH[3], bl0, bl1);
                mma_bf16(o[ni], aH[0], aH[1], aH[2], aH[3], bh0, bh1);
            }
        }
    }

    float inv0 = 1.f / l0, inv1 = 1.f / l1;
    int t0 = b * Ss + qt * 64 + w * 16 + lr;
    size_t base0 = (size_t)t0 * 1024 + h * 32;
    size_t base1 = base0 + (size_t)8 * 1024;
#pragma unroll
    for (int ni = 0; ni < 8; ni++) {
        int pi = ni * 4 + lc;
        uint32_t h0, l0w, h1, l1w;
        bf_split2(o[ni][0] * inv0, o[ni][1] * inv0, h0, l0w);
        bf_split2(o[ni][2] * inv1, o[ni][3] * inv1, h1, l1w);
        outH[base0 + pi] = h0; outL[base0 + pi] = l0w;
        outH[base1 + pi] = h1; outL[base1 + pi] = l1w;
    }
}

__global__ void router_kernel(const float* __restrict__ g, const float* __restrict__ rw,
                              int* __restrict__ cnt, int* __restrict__ idx,
                              float* __restrict__ sc, int* __restrict__ slot) {
    int t = blockIdx.x;
    int warp = threadIdx.x >> 5, lane = threadIdx.x & 31;
    const float* gr = g + (size_t)t * Dd;
    float acc = 0.f;
    for (int d = lane; d < Dd; d += 32) acc += gr[d] * rw[(size_t)d * Ee + warp];
    for (int o = 16; o; o >>= 1) acc += __shfl_xor_sync(0xffffffffu, acc, o);
    __shared__ float lg[Ee];
    if (lane == 0) lg[warp] = acc;
    __syncthreads();
    if (threadIdx.x == 0) {
        int b1 = 0;
        for (int e = 1; e < Ee; e++) if (lg[e] > lg[b1]) b1 = e;
        int b2 = -1;
        for (int e = 0; e < Ee; e++) {
            if (e == b1) continue;
            if (b2 < 0 || lg[e] > lg[b2]) b2 = e;
        }
        int p1 = atomicAdd(&cnt[b1], 1);
        idx[b1 * Ttok + p1] = t;
        sc [b1 * Ttok + p1] = 1.f / (1.f + expf(-lg[b1]));
        slot[t * 2 + 0] = b1 * Ttok + p1;
        int p2 = atomicAdd(&cnt[b2], 1);
        idx[b2 * Ttok + p2] = t;
        sc [b2 * Ttok + p2] = 1.f / (1.f + expf(-lg[b2]));
        slot[t * 2 + 1] = b2 * Ttok + p2;
    }
}

__global__ void act16_kernel(const float* __restrict__ gu, uint32_t* __restrict__ hid16,
                             const int* __restrict__ cnt) {
    long gidx = (long)blockIdx.x * 256 + threadIdx.x;
    int e = (int)(gidx / ((long)Ttok * 512));
    long rem = gidx % ((long)Ttok * 512);
    int m = (int)(rem >> 9);
    int i2 = (int)(rem & 511);
    int Meff = cnt ? cnt[e] : Ttok;
    if (m >= Meff) return;
    const float* gup = gu + (size_t)e * Ttok * 2048 + (size_t)m * 2048;
    float g0 = gup[2 * i2], g1 = gup[2 * i2 + 1];
    float u0 = gup[1024 + 2 * i2], u1 = gup[1024 + 2 * i2 + 1];
    float v0 = g0 / (1.f + expf(-g0)) * u0;
    float v1 = g1 / (1.f + expf(-g1)) * u1;
    hid16[(size_t)e * Ttok * 512 + (size_t)m * 512 + i2] = h2pack(v0, v1);
}

__global__ void add4_kernel(float* __restrict__ out, const float* __restrict__ h1,
                            const float* __restrict__ shd, const float* __restrict__ eo,
                            const int* __restrict__ slot) {
    int gid = blockIdx.x * 256 + threadIdx.x;
    int t = gid / (Dd / 4);
    int d4 = gid % (Dd / 4);
    size_t off = (size_t)t * Dd + d4 * 4;
    int s0 = slot[t * 2 + 0], s1 = slot[t * 2 + 1];
    float4 a = *(const float4*)(h1 + off);
    float4 b = *(const float4*)(shd + off);
    float4 c0 = *(const float4*)(eo + (size_t)s0 * Dd + d4 * 4);
    float4 c1 = *(const float4*)(eo + (size_t)s1 * Dd + d4 * 4);
    float4 r;
    r.x = a.x + b.x + c0.x + c1.x;
    r.y = a.y + b.y + c0.y + c1.y;
    r.z = a.z + b.z + c0.z + c1.z;
    r.w = a.w + b.w + c0.w + c1.w;
    *(float4*)(out + off) = r;
}

// ---------------- tensor-core GEMM on pre-converted 16-bit pair data (R11 form) ----
constexpr int KSTR = 136;

template<int GATHER_A, int CMODE, int PREC>
__global__ __launch_bounds__(128, 2)
void tgemm_kernel(const uint32_t* __restrict__ AH, const uint32_t* __restrict__ AL,
                  const uint32_t* __restrict__ BH, const uint32_t* __restrict__ BL,
                  float* __restrict__ C, const float* __restrict__ Cadd,
                  int M, int N, int K, int ldaP, int ldbN, int ldc,
                  const int* __restrict__ rowIdx, const float* __restrict__ rowScale,
                  const int* __restrict__ cntPtr,
                  long eAstrideP, long eBstrideP, long eCstride,
                  const uint32_t* __restrict__ BselH = nullptr) {
    int e = blockIdx.z;
    int Meff = cntPtr ? cntPtr[e] : M;
    int row0 = blockIdx.y * 128, col0 = blockIdx.x * 128;
    if (row0 >= Meff) return;

    extern __shared__ uint32_t dsm[];
    constexpr int perStage = 2 * 16 * KSTR;

    const int*   rI = rowIdx   ? rowIdx   + (size_t)e * Ttok : nullptr;
    const float* rS = rowScale ? rowScale + (size_t)e * Ttok : nullptr;
    const uint32_t* ApH = AH + (size_t)e * eAstrideP;
    const uint32_t* ApL = (PREC == 2) ? AL + (size_t)e * eAstrideP : nullptr;
    const uint32_t *BpH, *BpL = nullptr;
    float* Cp;
    if (BselH) {
        BpH = e ? BselH : BH;
        Cp = C + (size_t)e * eCstride;
    } else {
        BpH = BH + (size_t)e * eBstrideP;
        if (PREC == 2) BpL = BL + (size_t)e * eBstrideP;
        Cp = C + (size_t)e * eCstride;
    }

    int tid  = threadIdx.x;
    int lane = tid & 31;
    int wid  = tid >> 5;
    int warp_m = (wid & 1) * 64;
    int warp_n = (wid >> 1) * 64;
    int lr = lane >> 2, lc = lane & 3;

    int a_row = tid;
    int gm = row0 + a_row;
    bool avalid = (gm < Meff);
    const uint32_t* arH = ApH;
    const uint32_t* arL = ApL;
    if (avalid) {
        int src = GATHER_A ? rI[gm] : gm;
        arH = ApH + (size_t)src * ldaP;
        if (PREC == 2) arL = ApL + (size_t)src * ldaP;
    }
    int bp   = tid >> 4;
    int bpn0 = (tid & 15) * 8;

    float c[4][8][4];
#pragma unroll
    for (int mi = 0; mi < 4; mi++)
#pragma unroll
        for (int ni = 0; ni < 8; ni++)
#pragma unroll
            for (int r = 0; r < 4; r++) c[mi][ni][r] = 0.f;

    uint4 aW0h, aW1h, aW0l, aW1l, bW0h, bW1h, bW0l, bW1l;

    auto loadStage = [&](int k0) {
        int kp0 = k0 >> 1;
        if (avalid) {
            aW0h = *(const uint4*)(arH + kp0);
            aW1h = *(const uint4*)(arH + kp0 + 4);
            if (PREC == 2) {
                aW0l = *(const uint4*)(arL + kp0);
                aW1l = *(const uint4*)(arL + kp0 + 4);
            }
        } else {
            aW0h = aW1h = make_uint4(0, 0, 0, 0);
            if (PREC == 2) { aW0l = aW1l = make_uint4(0, 0, 0, 0); }
        }
        const uint32_t* br = BpH + (size_t)(kp0 + bp) * ldbN + col0 + bpn0;
        bW0h = *(const uint4*)br;
        bW1h = *(const uint4*)(br + 4);
        if (PREC == 2) {
            const uint32_t* brl = BpL + (size_t)(kp0 + bp) * ldbN + col0 + bpn0;
            bW0l = *(const uint4*)brl;
            bW1l = *(const uint4*)(brl + 4);
        }
    };

    auto storeStage = [&](int s) {
        uint32_t* APH = dsm + s * perStage;
        uint32_t* BPH = APH + 8 * KSTR;
        uint32_t* APL = BPH + 8 * KSTR;
        uint32_t* BPL = APL + 8 * KSTR;
        APH[0 * KSTR + a_row] = aW0h.x;
        APH[1 * KSTR + a_row] = aW0h.y;
        APH[2 * KSTR + a_row] = aW0h.z;
        APH[3 * KSTR + a_row] = aW0h.w;
        APH[4 * KSTR + a_row] = aW1h.x;
        APH[5 * KSTR + a_row] = aW1h.y;
        APH[6 * KSTR + a_row] = aW1h.z;
        APH[7 * KSTR + a_row] = aW1h.w;
        *(uint4*)&BPH[bp * KSTR + bpn0]     = bW0h;
        *(uint4*)&BPH[bp * KSTR + bpn0 + 4] = bW1h;
        if (PREC == 2) {
            APL[0 * KSTR + a_row] = aW0l.x;
            APL[1 * KSTR + a_row] = aW0l.y;
            APL[2 * KSTR + a_row] = aW0l.z;
            APL[3 * KSTR + a_row] = aW0l.w;
            APL[4 * KSTR + a_row] = aW1l.x;
            APL[5 * KSTR + a_row] = aW1l.y;
            APL[6 * KSTR + a_row] = aW1l.z;
            APL[7 * KSTR + a_row] = aW1l.w;
            *(uint4*)&BPL[bp * KSTR + bpn0]     = bW0l;
            *(uint4*)&BPL[bp * KSTR + bpn0 + 4] = bW1l;
        }
    };

    int nk = K >> 4;
    loadStage(0);
    storeStage(0);

    for (int kt = 0; kt < nk; kt++) {
        __syncthreads();
        bool more = (kt + 1) < nk;
        if (more) loadStage((kt + 1) << 4);

        int s = kt & 1;
        uint32_t* APH = dsm + s * perStage;
        uint32_t* BPH = APH + 8 * KSTR;
        uint32_t* APL = BPH + 8 * KSTR;
        uint32_t* BPL = APL + 8 * KSTR;

        uint32_t aH[4][4];
#pragma unroll
        for (int mi = 0; mi < 4; mi++) {
            int r = warp_m + mi * 16 + lr;
            aH[mi][0] = APH[lc * KSTR + r];
            aH[mi][1] = APH[lc * KSTR + r + 8];
            aH[mi][2] = APH[(lc + 4) * KSTR + r];
            aH[mi][3] = APH[(lc + 4) * KSTR + r + 8];
        }
        if (PREC == 1) {
#pragma unroll
            for (int ni = 0; ni < 8; ni++) {
                int cn = warp_n + ni * 8 + lr;
                uint32_t bh0 = BPH[lc * KSTR + cn];
                uint32_t bh1 = BPH[(lc + 4) * KSTR + cn];
#pragma unroll
                for (int mi = 0; mi < 4; mi++)
                    mma_f16(c[mi][ni], aH[mi][0], aH[mi][1], aH[mi][2], aH[mi][3],
                            bh0, bh1);
            }
        } else {
            uint32_t aL[4][4];
#pragma unroll
            for (int mi = 0; mi < 4; mi++) {
                int r = warp_m + mi * 16 + lr;
                aL[mi][0] = APL[lc * KSTR + r];
                aL[mi][1] = APL[lc * KSTR + r + 8];
                aL[mi][2] = APL[(lc + 4) * KSTR + r];
                aL[mi][3] = APL[(lc + 4) * KSTR + r + 8];
            }
#pragma unroll
            for (int ni = 0; ni < 8; ni++) {
                int cn = warp_n + ni * 8 + lr;
                uint32_t bh0 = BPH[lc * KSTR + cn];
                uint32_t bh1 = BPH[(lc + 4) * KSTR + cn];
                uint32_t bl0 = BPL[lc * KSTR + cn];
                uint32_t bl1 = BPL[(lc + 4) * KSTR + cn];
#pragma unroll
                for (int mi = 0; mi < 4; mi++) {
                    mma_bf16(c[mi][ni], aL[mi][0], aL[mi][1], aL[mi][2], aL[mi][3],
                             bh0, bh1);
                    mma_bf16(c[mi][ni], aH[mi][0], aH[mi][1], aH[mi][2], aH[mi][3],
                             bl0, bl1);
                    mma_bf16(c[mi][ni], aH[mi][0], aH[mi][1], aH[mi][2], aH[mi][3],
                             bh0, bh1);
                }
            }
        }
        if (more) storeStage((kt + 1) & 1);
    }

    // epilogue (rowScale applied here for gathered GEMMs)
#pragma unroll
    for (int mi = 0; mi < 4; mi++) {
        int r0 = row0 + warp_m + mi * 16 + lr;
        int r1 = r0 + 8;
#pragma unroll
        for (int ni = 0; ni < 8; ni++) {
            int cc = col0 + warp_n + ni * 8 + 2 * lc;
            if (r0 < Meff) {
                float s0 = GATHER_A ? rS[r0] : 1.f;
                float v0 = c[mi][ni][0] * s0, v1 = c[mi][ni][1] * s0;
                if (CMODE == 1) {
                    v0 += Cadd[(size_t)r0 * ldc + cc];
                    v1 += Cadd[(size_t)r0 * ldc + cc + 1];
                }
                float* cp = Cp + (size_t)r0 * ldc + cc;
                cp[0] = v0; cp[1] = v1;
            }
            if (r1 < Meff) {
                float s1 = GATHER_A ? rS[r1] : 1.f;
                float v2 = c[mi][ni][2] * s1, v3 = c[mi][ni][3] * s1;
                if (CMODE == 1) {
                    v2 += Cadd[(size_t)r1 * ldc + cc];
                    v3 += Cadd[(size_t)r1 * ldc + cc + 1];
                }
                float* cp = Cp + (size_t)r1 * ldc + cc;
                cp[0] = v2; cp[1] = v3;
            }
        }
    }
}

// ---------------- host orchestration ----------------
extern "C" void kernel_launch(void* const* d_in, const int* in_sizes, int n_in,
                              void* d_out, int out_size) {
    const float* x     = (const float*)d_in[0];
    const float* rope  = (const float*)d_in[2];
    const float* w_qkv = (const float*)d_in[4];
    const float* w_o   = (const float*)d_in[5];
    const float* n1    = (const float*)d_in[6];
    const float* n2    = (const float*)d_in[7];
    const float* rw    = (const float*)d_in[8];
    const float* wgu   = (const float*)d_in[9];
    const float* wdn   = (const float*)d_in[10];
    const float* sg    = (const float*)d_in[11];
    const float* su    = (const float*)d_in[12];
    const float* sd    = (const float*)d_in[13];
    float* out = (float*)d_out;

    float *qkv, *h1, *g, *shd, *gu, *eo, *sc;
    uint32_t *hH, *hL, *attnH, *attnL, *g16, *hid16;
    uint32_t *wqkvH, *wqkvL, *woH, *woL, *sg16, *su16, *sd16, *wgu16, *wdn16;
    int *cnt, *idx, *slot;
    cudaGetSymbolAddress((void**)&qkv,   g_qkv);
    cudaGetSymbolAddress((void**)&h1,    g_h1);
    cudaGetSymbolAddress((void**)&g,     g_g);
    cudaGetSymbolAddress((void**)&shd,   g_shd);
    cudaGetSymbolAddress((void**)&gu,    g_gu);
    cudaGetSymbolAddress((void**)&eo,    g_eo);
    cudaGetSymbolAddress((void**)&hH,    g_hH);
    cudaGetSymbolAddress((void**)&hL,    g_hL);
    cudaGetSymbolAddress((void**)&attnH, g_attnH);
    cudaGetSymbolAddress((void**)&attnL, g_attnL);
    cudaGetSymbolAddress((void**)&g16,   g_g16);
    cudaGetSymbolAddress((void**)&hid16, g_hid16);
    cudaGetSymbolAddress((void**)&wqkvH, g_wqkvH);
    cudaGetSymbolAddress((void**)&wqkvL, g_wqkvL);
    cudaGetSymbolAddress((void**)&woH,   g_woH);
    cudaGetSymbolAddress((void**)&woL,   g_woL);
    cudaGetSymbolAddress((void**)&sg16,  g_sg16);
    cudaGetSymbolAddress((void**)&su16,  g_su16);
    cudaGetSymbolAddress((void**)&sd16,  g_sd16);
    cudaGetSymbolAddress((void**)&wgu16, g_wgu16);
    cudaGetSymbolAddress((void**)&wdn16, g_wdn16);
    cudaGetSymbolAddress((void**)&cnt,   g_cnt);
    cudaGetSymbolAddress((void**)&idx,   g_idx);
    cudaGetSymbolAddress((void**)&sc,    g_sc);
    cudaGetSymbolAddress((void**)&slot,  g_slot);

    const int SMB = 2 * 2 * 16 * KSTR * 4;    // 34816 B

    zero_cnt_kernel<<<1, 32>>>(cnt);

    // ---- one-shot weight conversions (float4-vectorized, 8 words/thread) ----
    {
        long t1 = (long)1024 * 3072 / 8;
        convBbf2_kernel<<<(t1 + 255) / 256, 256>>>(w_qkv, wqkvH, wqkvL, 3072, t1);
        long t2 = (long)1024 * 2048 / 8;
        convBbf2_kernel<<<(t2 + 255) / 256, 256>>>(w_o, woH, woL, 2048, t2);
        long t3 = (long)1024 * 1024 / 8;
        convB16_kernel<<<(t3 + 255) / 256, 256>>>(sg, sg16, 1024, t3);
        convB16_kernel<<<(t3 + 255) / 256, 256>>>(su, su16, 1024, t3);
        long t4 = (long)512 * 2048 / 8;
        convB16_kernel<<<(t4 + 255) / 256, 256>>>(sd, sd16, 2048, t4);
        long t5 = (long)Ee * 1024 * 2048 / 8;
        convB16_kernel<<<(t5 + 255) / 256, 256>>>(wgu, wgu16, 2048, t5);
        long t6 = (long)Ee * 512 * 2048 / 8;
        convB16_kernel<<<(t6 + 255) / 256, 256>>>(wdn, wdn16, 2048, t6);
    }

    rmsnorm_bf2_kernel<<<Ttok, 256>>>(x, n1, hH, hL);

    // qkv = h @ w_qkv  (bf16x3)
    tgemm_kernel<0, 0, 2><<<dim3(QKVW / 128, Ttok / 128), 128, SMB>>>(
        hH, hL, wqkvH, wqkvL, qkv, nullptr,
        Ttok, QKVW, Dd, 1024, QKVW, QKVW,
        nullptr, nullptr, nullptr, 0, 0, 0);

    rope_kernel<<<(Ttok * 40 * 32 + 255) / 256, 256>>>(qkv, rope);

    attn_mma_kernel<<<dim3(Ss / 64, Hh, Bb), 128>>>(qkv, attnH, attnL);

    // h1 = x + attn @ w_o  (bf16x3)
    tgemm_kernel<0, 1, 2><<<dim3(Dd / 128, Ttok / 128), 128, SMB>>>(
        attnH, attnL, woH, woL, h1, x,
        Ttok, Dd, Dd, 1024, Dd, Dd,
        nullptr, nullptr, nullptr, 0, 0, 0);

    rmsnorm_f16_kernel<<<Ttok, 256>>>(h1, n2, g, g16);

    router_kernel<<<Ttok, 256>>>(g, rw, cnt, idx, sc, slot);

    // shared expert gate & up fused (fp16x1)
    tgemm_kernel<0, 0, 1><<<dim3(Ii / 128, Ttok / 128, 2), 128, SMB>>>(
        g16, nullptr, sg16, nullptr, gu, nullptr,
        Ttok, Ii, Dd, 1024, Ii, 2048,
        nullptr, nullptr, nullptr, 0, 0, 1024, su16);
    act16_kernel<<<(Ttok * 512) / 256, 256>>>(gu, hid16, nullptr);

    // shd = hid_shared @ shared_down (fp16x1)
    tgemm_kernel<0, 0, 1><<<dim3(Dd / 128, Ttok / 128), 128, SMB>>>(
        hid16, nullptr, sd16, nullptr, shd, nullptr,
        Ttok, Dd, Ii, 512, Dd, Dd,
        nullptr, nullptr, nullptr, 0, 0, 0);

    // routed experts gate_up (fp16x1, gathered A; scale in epilogue)
    tgemm_kernel<1, 0, 1><<<dim3(2048 / 128, Ttok / 128, Ee), 128, SMB>>>(
        g16, nullptr, wgu16, nullptr, gu, nullptr,
        Ttok, 2048, Dd, 1024, 2048, 2048,
        idx, sc, cnt, 0, (long)1024 * 2048, (long)Ttok * 2048);

    act16_kernel<<<(Ee * Ttok * 512) / 256, 256>>>(gu, hid16, cnt);

    // routed down projections (fp16x1)
    tgemm_kernel<0, 0, 1><<<dim3(Dd / 128, Ttok / 128, Ee), 128, SMB>>>(
        hid16, nullptr, wdn16, nullptr, eo, nullptr,
        Ttok, Dd, Ii, 512, Dd, Dd,
        nullptr, nullptr, cnt, (long)Ttok * 512, (long)512 * 2048, (long)Ttok * Dd);

    add4_kernel<<<(Ttok * Dd / 4) / 256, 256>>>(out, h1, shd, eo, slot);
}

// round 14
// speedup vs baseline: 1.6946x; 1.1197x over previous
#include <cuda_runtime.h>
#include <cuda_bf16.h>
#include <cuda_fp16.h>
#include <math.h>
#include <stdint.h>

// ---------------- problem constants ----------------
constexpr int Bb   = 2;
constexpr int Ss   = 1024;
constexpr int Dd   = 2048;
constexpr int Hh   = 32;
constexpr int HKV  = 8;
constexpr int HDh  = 64;
constexpr int Ee   = 8;
constexpr int Ii   = 1024;
constexpr int Ttok = Bb * Ss;
constexpr int QKVW = (Hh + 2 * HKV) * HDh;    // 3072
constexpr int KOFF = Hh * HDh;                // 2048
constexpr int VOFF = (Hh + HKV) * HDh;        // 2560

// ---------------- scratch ----------------
__device__ float g_qkv [(size_t)Ttok * QKVW];
__device__ float g_h1  [(size_t)Ttok * Dd];
__device__ float g_g   [(size_t)Ttok * Dd];
__device__ float g_shd [(size_t)Ttok * Dd];
__device__ float g_gu  [(size_t)Ee * Ttok * 2048];
__device__ float g_eo  [(size_t)Ee * Ttok * Dd];
__device__ uint32_t g_hH   [(size_t)Ttok * 1024];
__device__ uint32_t g_hL   [(size_t)Ttok * 1024];
__device__ uint32_t g_attnH[(size_t)Ttok * 1024];
__device__ uint32_t g_attnL[(size_t)Ttok * 1024];
__device__ uint32_t g_g16  [(size_t)Ttok * 1024];
__device__ uint32_t g_hid16[(size_t)Ee * Ttok * 512];
__device__ uint32_t g_wqkvH[(size_t)1024 * 3072];
__device__ uint32_t g_wqkvL[(size_t)1024 * 3072];
__device__ uint32_t g_woH  [(size_t)1024 * 2048];
__device__ uint32_t g_woL  [(size_t)1024 * 2048];
__device__ uint32_t g_sg16 [(size_t)1024 * 1024];
__device__ uint32_t g_su16 [(size_t)1024 * 1024];
__device__ uint32_t g_sd16 [(size_t)512 * 2048];
__device__ uint32_t g_wgu16[(size_t)Ee * 1024 * 2048];
__device__ uint32_t g_wdn16[(size_t)Ee * 512 * 2048];
// K/V bf16 hi/lo planes for attention
__device__ uint32_t g_kH[(size_t)16 * 1024 * 32];   // [b*8+kvh][kpos][32 d-pairs]
__device__ uint32_t g_kL[(size_t)16 * 1024 * 32];
__device__ uint32_t g_vH[(size_t)16 * 64 * 512];    // [b*8+kvh][d][512 kpos-pairs]
__device__ uint32_t g_vL[(size_t)16 * 64 * 512];
__device__ int   g_cnt [Ee];
__device__ int   g_idx [Ee * Ttok];
__device__ float g_sc  [Ee * Ttok];
__device__ int   g_slot[Ttok * 2];

// ---------------- helpers ----------------
__device__ __forceinline__ void mma_bf16(float c[4], uint32_t a0, uint32_t a1,
                                         uint32_t a2, uint32_t a3,
                                         uint32_t b0, uint32_t b1) {
    asm volatile(
        "mma.sync.aligned.m16n8k16.row.col.f32.bf16.bf16.f32 "
        "{%0,%1,%2,%3}, {%4,%5,%6,%7}, {%8,%9}, {%0,%1,%2,%3};"
        : "+f"(c[0]), "+f"(c[1]), "+f"(c[2]), "+f"(c[3])
        : "r"(a0), "r"(a1), "r"(a2), "r"(a3), "r"(b0), "r"(b1));
}

__device__ __forceinline__ void mma_f16(float c[4], uint32_t a0, uint32_t a1,
                                        uint32_t a2, uint32_t a3,
                                        uint32_t b0, uint32_t b1) {
    asm volatile(
        "mma.sync.aligned.m16n8k16.row.col.f32.f16.f16.f32 "
        "{%0,%1,%2,%3}, {%4,%5,%6,%7}, {%8,%9}, {%0,%1,%2,%3};"
        : "+f"(c[0]), "+f"(c[1]), "+f"(c[2]), "+f"(c[3])
        : "r"(a0), "r"(a1), "r"(a2), "r"(a3), "r"(b0), "r"(b1));
}

__device__ __forceinline__ void bf_split2(float x, float y, uint32_t& hi, uint32_t& lo) {
    __nv_bfloat16 hx = __float2bfloat16_rn(x);
    __nv_bfloat16 hy = __float2bfloat16_rn(y);
    float rx = x - __bfloat162float(hx);
    float ry = y - __bfloat162float(hy);
    __nv_bfloat16 lx = __float2bfloat16_rn(rx);
    __nv_bfloat16 ly = __float2bfloat16_rn(ry);
    hi = (uint32_t)__bfloat16_as_ushort(hx) | ((uint32_t)__bfloat16_as_ushort(hy) << 16);
    lo = (uint32_t)__bfloat16_as_ushort(lx) | ((uint32_t)__bfloat16_as_ushort(ly) << 16);
}

__device__ __forceinline__ uint32_t h2pack(float x, float y) {
    __half2 h = __floats2half2_rn(x, y);
    return *(uint32_t*)&h;
}

// ---------------- conversion kernels ----------------
__global__ void convB16_kernel(const float* __restrict__ src, uint32_t* __restrict__ dst,
                               int Nd, long tot8) {
    long i = (long)blockIdx.x * 256 + threadIdx.x;
    if (i >= tot8) return;
    int N8 = Nd >> 3;
    long kp = i / N8;
    int n8 = (int)(i - kp * N8);
    const float* s = src + (size_t)(2 * kp) * Nd + 8 * n8;
    float4 r0a = *(const float4*)s;
    float4 r0b = *(const float4*)(s + 4);
    float4 r1a = *(const float4*)(s + Nd);
    float4 r1b = *(const float4*)(s + Nd + 4);
    uint4 da, db;
    da.x = h2pack(r0a.x, r1a.x); da.y = h2pack(r0a.y, r1a.y);
    da.z = h2pack(r0a.z, r1a.z); da.w = h2pack(r0a.w, r1a.w);
    db.x = h2pack(r0b.x, r1b.x); db.y = h2pack(r0b.y, r1b.y);
    db.z = h2pack(r0b.z, r1b.z); db.w = h2pack(r0b.w, r1b.w);
    uint32_t* d = dst + (size_t)kp * Nd + 8 * n8;
    *(uint4*)d = da;
    *(uint4*)(d + 4) = db;
}

__global__ void convBbf2_kernel(const float* __restrict__ src, uint32_t* __restrict__ hi,
                                uint32_t* __restrict__ lo, int Nd, long tot8) {
    long i = (long)blockIdx.x * 256 + threadIdx.x;
    if (i >= tot8) return;
    int N8 = Nd >> 3;
    long kp = i / N8;
    int n8 = (int)(i - kp * N8);
    const float* s = src + (size_t)(2 * kp) * Nd + 8 * n8;
    float4 r0a = *(const float4*)s;
    float4 r0b = *(const float4*)(s + 4);
    float4 r1a = *(const float4*)(s + Nd);
    float4 r1b = *(const float4*)(s + Nd + 4);
    uint4 ha, la, hb, lb;
    bf_split2(r0a.x, r1a.x, ha.x, la.x);
    bf_split2(r0a.y, r1a.y, ha.y, la.y);
    bf_split2(r0a.z, r1a.z, ha.z, la.z);
    bf_split2(r0a.w, r1a.w, ha.w, la.w);
    bf_split2(r0b.x, r1b.x, hb.x, lb.x);
    bf_split2(r0b.y, r1b.y, hb.y, lb.y);
    bf_split2(r0b.z, r1b.z, hb.z, lb.z);
    bf_split2(r0b.w, r1b.w, hb.w, lb.w);
    uint32_t* ph = hi + (size_t)kp * Nd + 8 * n8;
    uint32_t* pl = lo + (size_t)kp * Nd + 8 * n8;
    *(uint4*)ph = ha; *(uint4*)(ph + 4) = hb;
    *(uint4*)pl = la; *(uint4*)(pl + 4) = lb;
}

// K/V planes for attention: K pair-packed along d; V transposed pair-packed along kpos
__global__ void convKV_kernel(const float* __restrict__ qkv,
                              uint32_t* __restrict__ KH, uint32_t* __restrict__ KL,
                              uint32_t* __restrict__ VH, uint32_t* __restrict__ VL) {
    int i = blockIdx.x * 256 + threadIdx.x;
    const int KTOT = 16 * 1024 * 32;
    if (i < KTOT) {
        int bk = i >> 15, rem = i & 32767;
        int kpos = rem >> 5, pi = rem & 31;
        int bq = bk >> 3, kvh = bk & 7;
        const float* s = qkv + ((size_t)(bq * Ss + kpos)) * QKVW + KOFF + kvh * 64 + 2 * pi;
        uint32_t h, l;
        bf_split2(s[0], s[1], h, l);
        KH[i] = h; KL[i] = l;
    } else {
        int j = i - KTOT;                 // [0, 16*64*512)
        if (j >= 16 * 64 * 512) return;
        int bk = j >> 15, rem = j & 32767;
        int d = rem >> 9, kp = rem & 511;
        int bq = bk >> 3, kvh = bk & 7;
        const float* s = qkv + ((size_t)(bq * Ss + 2 * kp)) * QKVW + VOFF + kvh * 64 + d;
        uint32_t h, l;
        bf_split2(s[0], s[QKVW], h, l);
        VH[j] = h; VL[j] = l;
    }
}

// ---------------- small kernels ----------------
__global__ void zero_cnt_kernel(int* cnt) {
    if (threadIdx.x < Ee) cnt[threadIdx.x] = 0;
}

__global__ void rmsnorm_bf2_kernel(const float* __restrict__ x, const float* __restrict__ w,
                                   uint32_t* __restrict__ hiA, uint32_t* __restrict__ loA) {
    int row = blockIdx.x;
    const float* xr = x + (size_t)row * Dd;
    float ss = 0.f;
    for (int i = threadIdx.x; i < Dd; i += 256) { float v = xr[i]; ss += v * v; }
    __shared__ float red[256];
    red[threadIdx.x] = ss; __syncthreads();
    for (int s = 128; s > 0; s >>= 1) {
        if (threadIdx.x < s) red[threadIdx.x] += red[threadIdx.x + s];
        __syncthreads();
    }
    float inv = rsqrtf(red[0] / (float)Dd + 1e-5f);
    for (int i = threadIdx.x; i < 1024; i += 256) {
        float v0 = xr[2 * i]     * inv * w[2 * i];
        float v1 = xr[2 * i + 1] * inv * w[2 * i + 1];
        uint32_t h, l;
        bf_split2(v0, v1, h, l);
        hiA[(size_t)row * 1024 + i] = h;
        loA[(size_t)row * 1024 + i] = l;
    }
}

__global__ void rmsnorm_f16_kernel(const float* __restrict__ x, const float* __restrict__ w,
                                   float* __restrict__ outF, uint32_t* __restrict__ out16) {
    int row = blockIdx.x;
    const float* xr = x + (size_t)row * Dd;
    float ss = 0.f;
    for (int i = threadIdx.x; i < Dd; i += 256) { float v = xr[i]; ss += v * v; }
    __shared__ float red[256];
    red[threadIdx.x] = ss; __syncthreads();
    for (int s = 128; s > 0; s >>= 1) {
        if (threadIdx.x < s) red[threadIdx.x] += red[threadIdx.x + s];
        __syncthreads();
    }
    float inv = rsqrtf(red[0] / (float)Dd + 1e-5f);
    float* orow = outF + (size_t)row * Dd;
    for (int i = threadIdx.x; i < 1024; i += 256) {
        float v0 = xr[2 * i]     * inv * w[2 * i];
        float v1 = xr[2 * i + 1] * inv * w[2 * i + 1];
        orow[2 * i]     = v0;
        orow[2 * i + 1] = v1;
        out16[(size_t)row * 1024 + i] = h2pack(v0, v1);
    }
}

__global__ void rope_kernel(float* __restrict__ qkv, const float* __restrict__ cache) {
    int idx = blockIdx.x * blockDim.x + threadIdx.x;
    const int TOT = Ttok * 40 * 32;
    if (idx >= TOT) return;
    int p  = idx & 31;
    int hh = (idx >> 5) % 40;
    int t  = idx / (32 * 40);
    int s  = t % Ss;
    float c  = cache[((size_t)s * 32 + p) * 2 + 0];
    float sn = cache[((size_t)s * 32 + p) * 2 + 1];
    float* base = qkv + (size_t)t * QKVW + hh * 64 + 2 * p;
    float x0 = base[0], x1 = base[1];
    base[0] = x0 * c - x1 * sn;
    base[1] = x1 * c + x0 * sn;
}

// ---------------- tensor-core flash attention (bf16x3, pre-converted K/V) ----------------
constexpr int AST = 36;

__global__ __launch_bounds__(128)
void attn_mma_kernel(const float* __restrict__ qkv,
                     const uint32_t* __restrict__ KHp, const uint32_t* __restrict__ KLp,
                     const uint32_t* __restrict__ VHp, const uint32_t* __restrict__ VLp,
                     uint32_t* __restrict__ outH, uint32_t* __restrict__ outL) {
    int qt = blockIdx.x, h = blockIdx.y, b = blockIdx.z;
    int tid = threadIdx.x, lane = tid & 31, w = tid >> 5;
    int lr = lane >> 2, lc = lane & 3;
    int kvh = h >> 2;
    size_t bk = (size_t)(b * 8 + kvh);

    __shared__ uint32_t KsH[64 * AST], KsL[64 * AST];
    __shared__ uint32_t VtH[64 * AST], VtL[64 * AST];

    uint32_t qh[4][4], ql[4][4];
    {
        int r0 = qt * 64 + w * 16 + lr;
        const float* q0p = qkv + ((size_t)(b * Ss + r0)) * QKVW + h * 64;
        const float* q1p = q0p + (size_t)8 * QKVW;
#pragma unroll
        for (int ck = 0; ck < 4; ck++) {
            float2 v00 = *(const float2*)(q0p + ck * 16 + 2 * lc);
            float2 v01 = *(const float2*)(q0p + ck * 16 + 8 + 2 * lc);
            float2 v10 = *(const float2*)(q1p + ck * 16 + 2 * lc);
            float2 v11 = *(const float2*)(q1p + ck * 16 + 8 + 2 * lc);
            bf_split2(v00.x * 0.125f, v00.y * 0.125f, qh[ck][0], ql[ck][0]);
            bf_split2(v10.x * 0.125f, v10.y * 0.125f, qh[ck][1], ql[ck][1]);
            bf_split2(v01.x * 0.125f, v01.y * 0.125f, qh[ck][2], ql[ck][2]);
            bf_split2(v11.x * 0.125f, v11.y * 0.125f, qh[ck][3], ql[ck][3]);
        }
    }

    float m0 = -1e30f, m1 = -1e30f, l0 = 0.f, l1 = 0.f;
    float o[8][4];
#pragma unroll
    for (int ni = 0; ni < 8; ni++)
#pragma unroll
        for (int r = 0; r < 4; r++) o[ni][r] = 0.f;

    for (int kt = 0; kt <= qt; kt++) {
        __syncthreads();
        {
            // K tile: thread handles row krow, 16 words at w0
            int krow = tid >> 1;
            int w0 = (tid & 1) * 16;
            const uint32_t* kh = KHp + (bk * 1024 + kt * 64 + krow) * 32 + w0;
            const uint32_t* kl = KLp + (bk * 1024 + kt * 64 + krow) * 32 + w0;
            uint32_t* dh = &KsH[krow * AST + w0];
            uint32_t* dl = &KsL[krow * AST + w0];
#pragma unroll
            for (int q = 0; q < 4; q++) {
                uint4 vh = *(const uint4*)(kh + 4 * q);
                uint4 vl = *(const uint4*)(kl + 4 * q);
                dh[4 * q + 0] = vh.x; dh[4 * q + 1] = vh.y;
                dh[4 * q + 2] = vh.z; dh[4 * q + 3] = vh.w;
                dl[4 * q + 0] = vl.x; dl[4 * q + 1] = vl.y;
                dl[4 * q + 2] = vl.z; dl[4 * q + 3] = vl.w;
            }
            // V tile: tid<64 -> VtH row d=tid; tid>=64 -> VtL row d=tid-64
            if (tid < 64) {
                int d = tid;
                const uint32_t* vp = VHp + (bk * 64 + d) * 512 + kt * 32;
                uint32_t* dst = &VtH[d * AST];
#pragma unroll
                for (int q = 0; q < 8; q++) {
                    uint4 v = *(const uint4*)(vp + 4 * q);
                    dst[4 * q + 0] = v.x; dst[4 * q + 1] = v.y;
                    dst[4 * q + 2] = v.z; dst[4 * q + 3] = v.w;
                }
            } else {
                int d = tid - 64;
                const uint32_t* vp = VLp + (bk * 64 + d) * 512 + kt * 32;
                uint32_t* dst = &VtL[d * AST];
#pragma unroll
                for (int q = 0; q < 8; q++) {
                    uint4 v = *(const uint4*)(vp + 4 * q);
                    dst[4 * q + 0] = v.x; dst[4 * q + 1] = v.y;
                    dst[4 * q + 2] = v.z; dst[4 * q + 3] = v.w;
                }
            }
        }
        __syncthreads();

        float s[8][4];
#pragma unroll
        for (int ni = 0; ni < 8; ni++)
#pragma unroll
            for (int r = 0; r < 4; r++) s[ni][r] = 0.f;
#pragma unroll
        for (int ck = 0; ck < 4; ck++) {
#pragma unroll
            for (int ni = 0; ni < 8; ni++) {
                int row = (ni * 8 + lr) * AST + ck * 8 + lc;
                uint32_t bh0 = KsH[row], bh1 = KsH[row + 4];
                uint32_t bl0 = KsL[row], bl1 = KsL[row + 4];
                mma_bf16(s[ni], ql[ck][0], ql[ck][1], ql[ck][2], ql[ck][3], bh0, bh1);
                mma_bf16(s[ni], qh[ck][0], qh[ck][1], qh[ck][2], qh[ck][3], bl0, bl1);
                mma_bf16(s[ni], qh[ck][0], qh[ck][1], qh[ck][2], qh[ck][3], bh0, bh1);
            }
        }

        if (kt == qt) {
            int lq0 = w * 16 + lr, lq1 = lq0 + 8;
#pragma unroll
            for (int ni = 0; ni < 8; ni++) {
                int col = ni * 8 + 2 * lc;
                if (col     > lq0) s[ni][0] = -1e30f;
                if (col + 1 > lq0) s[ni][1] = -1e30f;
                if (col     > lq1) s[ni][2] = -1e30f;
                if (col + 1 > lq1) s[ni][3] = -1e30f;
            }
        }

        float mt0 = -1e30f, mt1 = -1e30f;
#pragma unroll
        for (int ni = 0; ni < 8; ni++) {
            mt0 = fmaxf(mt0, fmaxf(s[ni][0], s[ni][1]));
            mt1 = fmaxf(mt1, fmaxf(s[ni][2], s[ni][3]));
        }
        mt0 = fmaxf(mt0, __shfl_xor_sync(0xffffffffu, mt0, 1));
        mt0 = fmaxf(mt0, __shfl_xor_sync(0xffffffffu, mt0, 2));
        mt1 = fmaxf(mt1, __shfl_xor_sync(0xffffffffu, mt1, 1));
        mt1 = fmaxf(mt1, __shfl_xor_sync(0xffffffffu, mt1, 2));
        float mn0 = fmaxf(m0, mt0), mn1 = fmaxf(m1, mt1);
        float sc0 = __expf(m0 - mn0), sc1 = __expf(m1 - mn1);
        m0 = mn0; m1 = mn1;

        float rs0 = 0.f, rs1 = 0.f;
#pragma unroll
        for (int ni = 0; ni < 8; ni++) {
            s[ni][0] = __expf(s[ni][0] - m0); rs0 += s[ni][0];
            s[ni][1] = __expf(s[ni][1] - m0); rs0 += s[ni][1];
            s[ni][2] = __expf(s[ni][2] - m1); rs1 += s[ni][2];
            s[ni][3] = __expf(s[ni][3] - m1); rs1 += s[ni][3];
        }
        rs0 += __shfl_xor_sync(0xffffffffu, rs0, 1);
        rs0 += __shfl_xor_sync(0xffffffffu, rs0, 2);
        rs1 += __shfl_xor_sync(0xffffffffu, rs1, 1);
        rs1 += __shfl_xor_sync(0xffffffffu, rs1, 2);
        l0 = l0 * sc0 + rs0;
        l1 = l1 * sc1 + rs1;

#pragma unroll
        for (int ni = 0; ni < 8; ni++) {
            o[ni][0] *= sc0; o[ni][1] *= sc0;
            o[ni][2] *= sc1; o[ni][3] *= sc1;
        }

#pragma unroll
        for (int ck = 0; ck < 4; ck++) {
            uint32_t aH[4], aL[4];
            bf_split2(s[2 * ck][0],     s[2 * ck][1],     aH[0], aL[0]);
            bf_split2(s[2 * ck][2],     s[2 * ck][3],     aH[1], aL[1]);
            bf_split2(s[2 * ck + 1][0], s[2 * ck + 1][1], aH[2], aL[2]);
            bf_split2(s[2 * ck + 1][2], s[2 * ck + 1][3], aH[3], aL[3]);
#pragma unroll
            for (int ni = 0; ni < 8; ni++) {
                int row = (ni * 8 + lr) * AST + ck * 8 + lc;
                uint32_t bh0 = VtH[row], bh1 = VtH[row + 4];
                uint32_t bl0 = VtL[row], bl1 = VtL[row + 4];
                mma_bf16(o[ni], aL[0], aL[1], aL[2], aL[3], bh0, bh1);
                mma_bf16(o[ni], aH[0], aH[1], aH[2], aH[3], bl0, bl1);
                mma_bf16(o[ni], aH[0], aH[1], aH[2], aH[3], bh0, bh1);
            }
        }
    }

    float inv0 = 1.f / l0, inv1 = 1.f / l1;
    int t0 = b * Ss + qt * 64 + w * 16 + lr;
    size_t base0 = (size_t)t0 * 1024 + h * 32;
    size_t base1 = base0 + (size_t)8 * 1024;
#pragma unroll
    for (int ni = 0; ni < 8; ni++) {
        int pi = ni * 4 + lc;
        uint32_t h0, l0w, h1, l1w;
        bf_split2(o[ni][0] * inv0, o[ni][1] * inv0, h0, l0w);
        bf_split2(o[ni][2] * inv1, o[ni][3] * inv1, h1, l1w);
        outH[base0 + pi] = h0; outL[base0 + pi] = l0w;
        outH[base1 + pi] = h1; outL[base1 + pi] = l1w;
    }
}

__global__ void router_kernel(const float* __restrict__ g, const float* __restrict__ rw,
                              int* __restrict__ cnt, int* __restrict__ idx,
                              float* __restrict__ sc, int* __restrict__ slot) {
    int t = blockIdx.x;
    int warp = threadIdx.x >> 5, lane = threadIdx.x & 31;
    const float* gr = g + (size_t)t * Dd;
    float acc = 0.f;
    for (int d = lane; d < Dd; d += 32) acc += gr[d] * rw[(size_t)d * Ee + warp];
    for (int o = 16; o; o >>= 1) acc += __shfl_xor_sync(0xffffffffu, acc, o);
    __shared__ float lg[Ee];
    if (lane == 0) lg[warp] = acc;
    __syncthreads();
    if (threadIdx.x == 0) {
        int b1 = 0;
        for (int e = 1; e < Ee; e++) if (lg[e] > lg[b1]) b1 = e;
        int b2 = -1;
        for (int e = 0; e < Ee; e++) {
            if (e == b1) continue;
            if (b2 < 0 || lg[e] > lg[b2]) b2 = e;
        }
        int p1 = atomicAdd(&cnt[b1], 1);
        idx[b1 * Ttok + p1] = t;
        sc [b1 * Ttok + p1] = 1.f / (1.f + expf(-lg[b1]));
        slot[t * 2 + 0] = b1 * Ttok + p1;
        int p2 = atomicAdd(&cnt[b2], 1);
        idx[b2 * Ttok + p2] = t;
        sc [b2 * Ttok + p2] = 1.f / (1.f + expf(-lg[b2]));
        slot[t * 2 + 1] = b2 * Ttok + p2;
    }
}

__global__ void act16_kernel(const float* __restrict__ gu, uint32_t* __restrict__ hid16,
                             const int* __restrict__ cnt) {
    long gidx = (long)blockIdx.x * 256 + threadIdx.x;
    int e = (int)(gidx / ((long)Ttok * 512));
    long rem = gidx % ((long)Ttok * 512);
    int m = (int)(rem >> 9);
    int i2 = (int)(rem & 511);
    int Meff = cnt ? cnt[e] : Ttok;
    if (m >= Meff) return;
    const float* gup = gu + (size_t)e * Ttok * 2048 + (size_t)m * 2048;
    float g0 = gup[2 * i2], g1 = gup[2 * i2 + 1];
    float u0 = gup[1024 + 2 * i2], u1 = gup[1024 + 2 * i2 + 1];
    float v0 = g0 / (1.f + expf(-g0)) * u0;
    float v1 = g1 / (1.f + expf(-g1)) * u1;
    hid16[(size_t)e * Ttok * 512 + (size_t)m * 512 + i2] = h2pack(v0, v1);
}

__global__ void add4_kernel(float* __restrict__ out, const float* __restrict__ h1,
                            const float* __restrict__ shd, const float* __restrict__ eo,
                            const int* __restrict__ slot) {
    int gid = blockIdx.x * 256 + threadIdx.x;
    int t = gid / (Dd / 4);
    int d4 = gid % (Dd / 4);
    size_t off = (size_t)t * Dd + d4 * 4;
    int s0 = slot[t * 2 + 0], s1 = slot[t * 2 + 1];
    float4 a = *(const float4*)(h1 + off);
    float4 b = *(const float4*)(shd + off);
    float4 c0 = *(const float4*)(eo + (size_t)s0 * Dd + d4 * 4);
    float4 c1 = *(const float4*)(eo + (size_t)s1 * Dd + d4 * 4);
    float4 r;
    r.x = a.x + b.x + c0.x + c1.x;
    r.y = a.y + b.y + c0.y + c1.y;
    r.z = a.z + b.z + c0.z + c1.z;
    r.w = a.w + b.w + c0.w + c1.w;
    *(float4*)(out + off) = r;
}

// ---------------- tensor-core GEMM on pre-converted 16-bit pair data ----------------
constexpr int KSTR = 136;

template<int GATHER_A, int CMODE, int PREC>
__global__ __launch_bounds__(128, 2)
void tgemm_kernel(const uint32_t* __restrict__ AH, const uint32_t* __restrict__ AL,
                  const uint32_t* __restrict__ BH, const uint32_t* __restrict__ BL,
                  float* __restrict__ C, const float* __restrict__ Cadd,
                  int M, int N, int K, int ldaP, int ldbN, int ldc,
                  const int* __restrict__ rowIdx, const float* __restrict__ rowScale,
                  const int* __restrict__ cntPtr,
                  long eAstrideP, long eBstrideP, long eCstride,
                  const uint32_t* __restrict__ BselH = nullptr) {
    int e = blockIdx.z;
    int Meff = cntPtr ? cntPtr[e] : M;
    int row0 = blockIdx.y * 128, col0 = blockIdx.x * 128;
    if (row0 >= Meff) return;

    extern __shared__ uint32_t dsm[];
    constexpr int perStage = 2 * 16 * KSTR;

    const int*   rI = rowIdx   ? rowIdx   + (size_t)e * Ttok : nullptr;
    const float* rS = rowScale ? rowScale + (size_t)e * Ttok : nullptr;
    const uint32_t* ApH = AH + (size_t)e * eAstrideP;
    const uint32_t* ApL = (PREC == 2) ? AL + (size_t)e * eAstrideP : nullptr;
    const uint32_t *BpH, *BpL = nullptr;
    float* Cp;
    if (BselH) {
        BpH = e ? BselH : BH;
        Cp = C + (size_t)e * eCstride;
    } else {
        BpH = BH + (size_t)e * eBstrideP;
        if (PREC == 2) BpL = BL + (size_t)e * eBstrideP;
        Cp = C + (size_t)e * eCstride;
    }

    int tid  = threadIdx.x;
    int lane = tid & 31;
    int wid  = tid >> 5;
    int warp_m = (wid & 1) * 64;
    int warp_n = (wid >> 1) * 64;
    int lr = lane >> 2, lc = lane & 3;

    int a_row = tid;
    int gm = row0 + a_row;
    bool avalid = (gm < Meff);
    const uint32_t* arH = ApH;
    const uint32_t* arL = ApL;
    if (avalid) {
        int src = GATHER_A ? rI[gm] : gm;
        arH = ApH + (size_t)src * ldaP;
        if (PREC == 2) arL = ApL + (size_t)src * ldaP;
    }
    int bp   = tid >> 4;
    int bpn0 = (tid & 15) * 8;

    float c[4][8][4];
#pragma unroll
    for (int mi = 0; mi < 4; mi++)
#pragma unroll
        for (int ni = 0; ni < 8; ni++)
#pragma unroll
            for (int r = 0; r < 4; r++) c[mi][ni][r] = 0.f;

    uint4 aW0h, aW1h, aW0l, aW1l, bW0h, bW1h, bW0l, bW1l;

    auto loadStage = [&](int k0) {
        int kp0 = k0 >> 1;
        if (avalid) {
            aW0h = *(const uint4*)(arH + kp0);
            aW1h = *(const uint4*)(arH + kp0 + 4);
            if (PREC == 2) {
                aW0l = *(const uint4*)(arL + kp0);
                aW1l = *(const uint4*)(arL + kp0 + 4);
            }
        } else {
            aW0h = aW1h = make_uint4(0, 0, 0, 0);
            if (PREC == 2) { aW0l = aW1l = make_uint4(0, 0, 0, 0); }
        }
        const uint32_t* br = BpH + (size_t)(kp0 + bp) * ldbN + col0 + bpn0;
        bW0h = *(const uint4*)br;
        bW1h = *(const uint4*)(br + 4);
        if (PREC == 2) {
            const uint32_t* brl = BpL + (size_t)(kp0 + bp) * ldbN + col0 + bpn0;
            bW0l = *(const uint4*)brl;
            bW1l = *(const uint4*)(brl + 4);
        }
    };

    auto storeStage = [&](int s) {
        uint32_t* APH = dsm + s * perStage;
        uint32_t* BPH = APH + 8 * KSTR;
        uint32_t* APL = BPH + 8 * KSTR;
        uint32_t* BPL = APL + 8 * KSTR;
        APH[0 * KSTR + a_row] = aW0h.x;
        APH[1 * KSTR + a_row] = aW0h.y;
        APH[2 * KSTR + a_row] = aW0h.z;
        APH[3 * KSTR + a_row] = aW0h.w;
        APH[4 * KSTR + a_row] = aW1h.x;
        APH[5 * KSTR + a_row] = aW1h.y;
        APH[6 * KSTR + a_row] = aW1h.z;
        APH[7 * KSTR + a_row] = aW1h.w;
        *(uint4*)&BPH[bp * KSTR + bpn0]     = bW0h;
        *(uint4*)&BPH[bp * KSTR + bpn0 + 4] = bW1h;
        if (PREC == 2) {
            APL[0 * KSTR + a_row] = aW0l.x;
            APL[1 * KSTR + a_row] = aW0l.y;
            APL[2 * KSTR + a_row] = aW0l.z;
            APL[3 * KSTR + a_row] = aW0l.w;
            APL[4 * KSTR + a_row] = aW1l.x;
            APL[5 * KSTR + a_row] = aW1l.y;
            APL[6 * KSTR + a_row] = aW1l.z;
            APL[7 * KSTR + a_row] = aW1l.w;
            *(uint4*)&BPL[bp * KSTR + bpn0]     = bW0l;
            *(uint4*)&BPL[bp * KSTR + bpn0 + 4] = bW1l;
        }
    };

    int nk = K >> 4;
    loadStage(0);
    storeStage(0);

    for (int kt = 0; kt < nk; kt++) {
        __syncthreads();
        bool more = (kt + 1) < nk;
        if (more) loadStage((kt + 1) << 4);

        int s = kt & 1;
        uint32_t* APH = dsm + s * perStage;
        uint32_t* BPH = APH + 8 * KSTR;
        uint32_t* APL = BPH + 8 * KSTR;
        uint32_t* BPL = APL + 8 * KSTR;

        uint32_t aH[4][4];
#pragma unroll
        for (int mi = 0; mi < 4; mi++) {
            int r = warp_m + mi * 16 + lr;
            aH[mi][0] = APH[lc * KSTR + r];
            aH[mi][1] = APH[lc * KSTR + r + 8];
            aH[mi][2] = APH[(lc + 4) * KSTR + r];
            aH[mi][3] = APH[(lc + 4) * KSTR + r + 8];
        }
        if (PREC == 1) {
#pragma unroll
            for (int ni = 0; ni < 8; ni++) {
                int cn = warp_n + ni * 8 + lr;
                uint32_t bh0 = BPH[lc * KSTR + cn];
                uint32_t bh1 = BPH[(lc + 4) * KSTR + cn];
#pragma unroll
                for (int mi = 0; mi < 4; mi++)
                    mma_f16(c[mi][ni], aH[mi][0], aH[mi][1], aH[mi][2], aH[mi][3],
                            bh0, bh1);
            }
        } else {
            uint32_t aL[4][4];
#pragma unroll
            for (int mi = 0; mi < 4; mi++) {
                int r = warp_m + mi * 16 + lr;
                aL[mi][0] = APL[lc * KSTR + r];
                aL[mi][1] = APL[lc * KSTR + r + 8];
                aL[mi][2] = APL[(lc + 4) * KSTR + r];
                aL[mi][3] = APL[(lc + 4) * KSTR + r + 8];
            }
#pragma unroll
            for (int ni = 0; ni < 8; ni++) {
                int cn = warp_n + ni * 8 + lr;
                uint32_t bh0 = BPH[lc * KSTR + cn];
                uint32_t bh1 = BPH[(lc + 4) * KSTR + cn];
                uint32_t bl0 = BPL[lc * KSTR + cn];
                uint32_t bl1 = BPL[(lc + 4) * KSTR + cn];
#pragma unroll
                for (int mi = 0; mi < 4; mi++) {
                    mma_bf16(c[mi][ni], aL[mi][0], aL[mi][1], aL[mi][2], aL[mi][3],
                             bh0, bh1);
                    mma_bf16(c[mi][ni], aH[mi][0], aH[mi][1], aH[mi][2], aH[mi][3],
                             bl0, bl1);
                    mma_bf16(c[mi][ni], aH[mi][0], aH[mi][1], aH[mi][2], aH[mi][3],
                             bh0, bh1);
                }
            }
        }
        if (more) storeStage((kt + 1) & 1);
    }

    // epilogue (rowScale applied here for gathered GEMMs)
#pragma unroll
    for (int mi = 0; mi < 4; mi++) {
        int r0 = row0 + warp_m + mi * 16 + lr;
        int r1 = r0 + 8;
#pragma unroll
        for (int ni = 0; ni < 8; ni++) {
            int cc = col0 + warp_n + ni * 8 + 2 * lc;
            if (r0 < Meff) {
                float s0 = GATHER_A ? rS[r0] : 1.f;
                float v0 = c[mi][ni][0] * s0, v1 = c[mi][ni][1] * s0;
                if (CMODE == 1) {
                    v0 += Cadd[(size_t)r0 * ldc + cc];
                    v1 += Cadd[(size_t)r0 * ldc + cc + 1];
                }
                float* cp = Cp + (size_t)r0 * ldc + cc;
                cp[0] = v0; cp[1] = v1;
            }
            if (r1 < Meff) {
                float s1 = GATHER_A ? rS[r1] : 1.f;
                float v2 = c[mi][ni][2] * s1, v3 = c[mi][ni][3] * s1;
                if (CMODE == 1) {
                    v2 += Cadd[(size_t)r1 * ldc + cc];
                    v3 += Cadd[(size_t)r1 * ldc + cc + 1];
                }
                float* cp = Cp + (size_t)r1 * ldc + cc;
                cp[0] = v2; cp[1] = v3;
            }
        }
    }
}

// ---------------- host orchestration ----------------
extern "C" void kernel_launch(void* const* d_in, const int* in_sizes, int n_in,
                              void* d_out, int out_size) {
    const float* x     = (const float*)d_in[0];
    const float* rope  = (const float*)d_in[2];
    const float* w_qkv = (const float*)d_in[4];
    const float* w_o   = (const float*)d_in[5];
    const float* n1    = (const float*)d_in[6];
    const float* n2    = (const float*)d_in[7];
    const float* rw    = (const float*)d_in[8];
    const float* wgu   = (const float*)d_in[9];
    const float* wdn   = (const float*)d_in[10];
    const float* sg    = (const float*)d_in[11];
    const float* su    = (const float*)d_in[12];
    const float* sd    = (const float*)d_in[13];
    float* out = (float*)d_out;

    float *qkv, *h1, *g, *shd, *gu, *eo, *sc;
    uint32_t *hH, *hL, *attnH, *attnL, *g16, *hid16;
    uint32_t *wqkvH, *wqkvL, *woH, *woL, *sg16, *su16, *sd16, *wgu16, *wdn16;
    uint32_t *kH, *kL, *vH, *vL;
    int *cnt, *idx, *slot;
    cudaGetSymbolAddress((void**)&qkv,   g_qkv);
    cudaGetSymbolAddress((void**)&h1,    g_h1);
    cudaGetSymbolAddress((void**)&g,     g_g);
    cudaGetSymbolAddress((void**)&shd,   g_shd);
    cudaGetSymbolAddress((void**)&gu,    g_gu);
    cudaGetSymbolAddress((void**)&eo,    g_eo);
    cudaGetSymbolAddress((void**)&hH,    g_hH);
    cudaGetSymbolAddress((void**)&hL,    g_hL);
    cudaGetSymbolAddress((void**)&attnH, g_attnH);
    cudaGetSymbolAddress((void**)&attnL, g_attnL);
    cudaGetSymbolAddress((void**)&g16,   g_g16);
    cudaGetSymbolAddress((void**)&hid16, g_hid16);
    cudaGetSymbolAddress((void**)&wqkvH, g_wqkvH);
    cudaGetSymbolAddress((void**)&wqkvL, g_wqkvL);
    cudaGetSymbolAddress((void**)&woH,   g_woH);
    cudaGetSymbolAddress((void**)&woL,   g_woL);
    cudaGetSymbolAddress((void**)&sg16,  g_sg16);
    cudaGetSymbolAddress((void**)&su16,  g_su16);
    cudaGetSymbolAddress((void**)&sd16,  g_sd16);
    cudaGetSymbolAddress((void**)&wgu16, g_wgu16);
    cudaGetSymbolAddress((void**)&wdn16, g_wdn16);
    cudaGetSymbolAddress((void**)&kH,    g_kH);
    cudaGetSymbolAddress((void**)&kL,    g_kL);
    cudaGetSymbolAddress((void**)&vH,    g_vH);
    cudaGetSymbolAddress((void**)&vL,    g_vL);
    cudaGetSymbolAddress((void**)&cnt,   g_cnt);
    cudaGetSymbolAddress((void**)&idx,   g_idx);
    cudaGetSymbolAddress((void**)&sc,    g_sc);
    cudaGetSymbolAddress((void**)&slot,  g_slot);

    const int SMB = 2 * 2 * 16 * KSTR * 4;    // 34816 B

    zero_cnt_kernel<<<1, 32>>>(cnt);

    // ---- one-shot weight conversions ----
    {
        long t1 = (long)1024 * 3072 / 8;
        convBbf2_kernel<<<(t1 + 255) / 256, 256>>>(w_qkv, wqkvH, wqkvL, 3072, t1);
        long t2 = (long)1024 * 2048 / 8;
        convBbf2_kernel<<<(t2 + 255) / 256, 256>>>(w_o, woH, woL, 2048, t2);
        long t3 = (long)1024 * 1024 / 8;
        convB16_kernel<<<(t3 + 255) / 256, 256>>>(sg, sg16, 1024, t3);
        convB16_kernel<<<(t3 + 255) / 256, 256>>>(su, su16, 1024, t3);
        long t4 = (long)512 * 2048 / 8;
        convB16_kernel<<<(t4 + 255) / 256, 256>>>(sd, sd16, 2048, t4);
        long t5 = (long)Ee * 1024 * 2048 / 8;
        convB16_kernel<<<(t5 + 255) / 256, 256>>>(wgu, wgu16, 2048, t5);
        long t6 = (long)Ee * 512 * 2048 / 8;
        convB16_kernel<<<(t6 + 255) / 256, 256>>>(wdn, wdn16, 2048, t6);
    }

    rmsnorm_bf2_kernel<<<Ttok, 256>>>(x, n1, hH, hL);

    // qkv = h @ w_qkv  (bf16x3)
    tgemm_kernel<0, 0, 2><<<dim3(QKVW / 128, Ttok / 128), 128, SMB>>>(
        hH, hL, wqkvH, wqkvL, qkv, nullptr,
        Ttok, QKVW, Dd, 1024, QKVW, QKVW,
        nullptr, nullptr, nullptr, 0, 0, 0);

    rope_kernel<<<(Ttok * 40 * 32 + 255) / 256, 256>>>(qkv, rope);

    // pre-convert roped K and V to bf16 hi/lo planes (once)
    convKV_kernel<<<(16 * 1024 * 32 + 16 * 64 * 512 + 255) / 256, 256>>>(
        qkv, kH, kL, vH, vL);

    attn_mma_kernel<<<dim3(Ss / 64, Hh, Bb), 128>>>(qkv, kH, kL, vH, vL, attnH, attnL);

    // h1 = x + attn @ w_o  (bf16x3)
    tgemm_kernel<0, 1, 2><<<dim3(Dd / 128, Ttok / 128), 128, SMB>>>(
        attnH, attnL, woH, woL, h1, x,
        Ttok, Dd, Dd, 1024, Dd, Dd,
        nullptr, nullptr, nullptr, 0, 0, 0);

    rmsnorm_f16_kernel<<<Ttok, 256>>>(h1, n2, g, g16);

    router_kernel<<<Ttok, 256>>>(g, rw, cnt, idx, sc, slot);

    // shared expert gate & up fused (fp16x1)
    tgemm_kernel<0, 0, 1><<<dim3(Ii / 128, Ttok / 128, 2), 128, SMB>>>(
        g16, nullptr, sg16, nullptr, gu, nullptr,
        Ttok, Ii, Dd, 1024, Ii, 2048,
        nullptr, nullptr, nullptr, 0, 0, 1024, su16);
    act16_kernel<<<(Ttok * 512) / 256, 256>>>(gu, hid16, nullptr);

    // shd = hid_shared @ shared_down (fp16x1)
    tgemm_kernel<0, 0, 1><<<dim3(Dd / 128, Ttok / 128), 128, SMB>>>(
        hid16, nullptr, sd16, nullptr, shd, nullptr,
        Ttok, Dd, Ii, 512, Dd, Dd,
        nullptr, nullptr, nullptr, 0, 0, 0);

    // routed experts gate_up (fp16x1, gathered A; scale in epilogue)
    tgemm_kernel<1, 0, 1><<<dim3(2048 / 128, Ttok / 128, Ee), 128, SMB>>>(
        g16, nullptr, wgu16, nullptr, gu, nullptr,
        Ttok, 2048, Dd, 1024, 2048, 2048,
        idx, sc, cnt, 0, (long)1024 * 2048, (long)Ttok * 2048);

    act16_kernel<<<(Ee * Ttok * 512) / 256, 256>>>(gu, hid16, cnt);

    // routed down projections (fp16x1)
    tgemm_kernel<0, 0, 1><<<dim3(Dd / 128, Ttok / 128, Ee), 128, SMB>>>(
        hid16, nullptr, wdn16, nullptr, eo, nullptr,
        Ttok, Dd, Ii, 512, Dd, Dd,
        nullptr, nullptr, cnt, (long)Ttok * 512, (long)512 * 2048, (long)Ttok * Dd);

    add4_kernel<<<(Ttok * Dd / 4) / 256, 256>>>(out, h1, shd, eo, slot);
}